// round 11
// baseline (speedup 1.0000x reference)
#include <cuda_runtime.h>
#include <cuda_fp16.h>
#include <math.h>

#define NB 2
#define HH 256
#define WW 256
#define HW 65536
#define DHW 16384   // 128*128
#define PAD 72      // fp16 row stride for ldmatrix tiles (attention)
#define RSTR 66     // attention raw fp32 row stride
#define NSLAB 16
#define PADX 136    // conv x smem row stride in halves ([k][px], 128 px + 8 pad)
#define PADK 40     // conv w smem row stride in halves ([oc][k])

// ---------------- scratch (static device allocations) ----------------
__device__ float g_US [NB*96 *HW];
__device__ float g_SU [NB*189*HW];
__device__ float g_WARP[NB*128*HW];
__device__ float g_DSS[NB*128*DHW];
__device__ float g_DSE[NB*128*HW];
__device__ float g_ATT[NB*64 *HW];
__device__ float g_H1 [NB*128*HW];
__device__ float g_S[192];
__device__ float g_T[192];
__device__ float g_PSUM[192*NSLAB];
__device__ float g_PSQ [192*NSLAB];

// ---------------- BN stats stage 1 ----------------
__global__ void bn_stats1_kernel(const float* __restrict__ src0, int C0,
                                 const float* __restrict__ src1, int C1,
                                 int hw) {
    int c = blockIdx.x;
    int slab = blockIdx.y;
    const float* base; int cs;
    if (c < C0) { base = src0 + (size_t)c * hw; cs = C0; }
    else        { base = src1 + (size_t)(c - C0) * hw; cs = C1; }
    int sl = hw / NSLAB;
    float sum = 0.f, sq = 0.f;
    for (int n = 0; n < NB; n++) {
        const float4* p = (const float4*)(base + (size_t)n * cs * hw + (size_t)slab * sl);
        int nv = sl >> 2;
        for (int i = threadIdx.x; i < nv; i += blockDim.x) {
            float4 v = p[i];
            sum += v.x + v.y + v.z + v.w;
            sq  += v.x*v.x + v.y*v.y + v.z*v.z + v.w*v.w;
        }
    }
    __shared__ float ssum[256], ssq[256];
    ssum[threadIdx.x] = sum; ssq[threadIdx.x] = sq; __syncthreads();
    for (int o = 128; o > 0; o >>= 1) {
        if (threadIdx.x < o) { ssum[threadIdx.x] += ssum[threadIdx.x+o]; ssq[threadIdx.x] += ssq[threadIdx.x+o]; }
        __syncthreads();
    }
    if (threadIdx.x == 0) {
        g_PSUM[c*NSLAB + slab] = ssum[0];
        g_PSQ [c*NSLAB + slab] = ssq[0];
    }
}

// ---------------- BN stats stage 2 ----------------
__global__ void bn_stats2_kernel(const float* __restrict__ g, const float* __restrict__ b,
                                 int hw) {
    int c = blockIdx.x;
    if (threadIdx.x == 0) {
        float sum = 0.f, sq = 0.f;
        #pragma unroll
        for (int s = 0; s < NSLAB; s++) { sum += g_PSUM[c*NSLAB + s]; sq += g_PSQ[c*NSLAB + s]; }
        float inv = 1.f / (float)(NB * hw);
        float m = sum * inv;
        float v = sq * inv - m * m;
        float s = g[c] * rsqrtf(v + 1e-5f);
        g_S[c] = s; g_T[c] = b[c] - m * s;
    }
}

// ---------------- mma helpers ----------------
__device__ __forceinline__ void ldm4(unsigned& r0, unsigned& r1, unsigned& r2, unsigned& r3,
                                     const __half* p) {
    unsigned a = (unsigned)__cvta_generic_to_shared(p);
    asm volatile("ldmatrix.sync.aligned.m8n8.x4.shared.b16 {%0,%1,%2,%3}, [%4];"
                 : "=r"(r0), "=r"(r1), "=r"(r2), "=r"(r3) : "r"(a));
}
__device__ __forceinline__ void ldm4t(unsigned& r0, unsigned& r1, unsigned& r2, unsigned& r3,
                                      const __half* p) {
    unsigned a = (unsigned)__cvta_generic_to_shared(p);
    asm volatile("ldmatrix.sync.aligned.m8n8.x4.trans.shared.b16 {%0,%1,%2,%3}, [%4];"
                 : "=r"(r0), "=r"(r1), "=r"(r2), "=r"(r3) : "r"(a));
}
__device__ __forceinline__ void mma16816(float* d, unsigned a0, unsigned a1, unsigned a2, unsigned a3,
                                         unsigned b0, unsigned b1) {
    asm volatile("mma.sync.aligned.m16n8k16.row.col.f32.f16.f16.f32 "
                 "{%0,%1,%2,%3}, {%4,%5,%6,%7}, {%8,%9}, {%0,%1,%2,%3};"
                 : "+f"(d[0]), "+f"(d[1]), "+f"(d[2]), "+f"(d[3])
                 : "r"(a0), "r"(a1), "r"(a2), "r"(a3), "r"(b0), "r"(b1));
}
__device__ __forceinline__ unsigned packh2(float lo, float hi) {
    __half2 h = __floats2half2_rn(lo, hi);
    return *(unsigned*)&h;
}

// ---------------- fused BN + conv1x1, tensor-core fp16 hi/lo split + reg double-buffer ----------------
// block tile: 128 px x 128 oc; 256 threads = 8 warps; warp = 16 px (1 m16 tile) x 128 oc
__global__ __launch_bounds__(256)
void conv1x1_tc_kernel(const float* __restrict__ src0, int C0,
                       const float* __restrict__ src1, int C1,
                       const float* __restrict__ w, const float* __restrict__ bias,
                       int Cout, int hw, float* __restrict__ out, int outStride, int relu,
                       float* __restrict__ mirror) {
    extern __shared__ char cvsm[];
    __half* xh = (__half*)cvsm;            // 32 x PADX halves
    __half* xl = xh + 32*PADX;
    __half* wh = xl + 32*PADX;             // 128 x PADK halves
    __half* wl = wh + 128*PADK;
    const int Cin = C0 + C1;
    int tid = threadIdx.x;
    int lane = tid & 31;
    int wid = tid >> 5;                    // 0..7
    int g = lane >> 2, t = lane & 3;
    int p0 = blockIdx.x * 128;
    int n = p0 / hw, hw0 = p0 % hw;
    int ot = blockIdx.y;

    float acc[16][4];
    #pragma unroll
    for (int j = 0; j < 16; j++)
        #pragma unroll
        for (int e = 0; e < 4; e++) acc[j][e] = 0.f;

    float4 xv[4];
    float4 wv[4];
    float  sS[4], sT[4];

    // ---- prologue: load slab 0 into registers ----
    #pragma unroll
    for (int it = 0; it < 4; it++) {
        int idx = tid + it * 256;          // 0..1023
        int c = idx >> 5, p4 = idx & 31;
        const float* src = (c < C0) ? (src0 + (size_t)(n*C0 + c) * hw)
                                    : (src1 + (size_t)(n*C1 + (c - C0)) * hw);
        xv[it] = *(const float4*)(src + hw0 + p4*4);
        sS[it] = g_S[c]; sT[it] = g_T[c];
    }
    #pragma unroll
    for (int it = 0; it < 4; it++) {
        int idx = tid + it * 256;          // 0..1023
        int o = idx >> 3, k4 = idx & 7;
        int oc = ot*128 + o;
        if (oc < Cout) wv[it] = *(const float4*)(w + (size_t)oc * Cin + k4*4);
        else { wv[it].x = 0.f; wv[it].y = 0.f; wv[it].z = 0.f; wv[it].w = 0.f; }
    }

    for (int cc = 0; cc < Cin; cc += 32) {
        // ---- convert registers -> smem ----
        #pragma unroll
        for (int it = 0; it < 4; it++) {
            int idx = tid + it * 256;
            int c = idx >> 5, p4 = idx & 31;
            float s = sS[it], tt = sT[it];
            float f0 = xv[it].x*s + tt, f1 = xv[it].y*s + tt;
            float f2 = xv[it].z*s + tt, f3 = xv[it].w*s + tt;
            __half h0 = __float2half_rn(f0), h1 = __float2half_rn(f1);
            __half h2 = __float2half_rn(f2), h3 = __float2half_rn(f3);
            __half l0 = __float2half_rn(f0 - __half2float(h0));
            __half l1 = __float2half_rn(f1 - __half2float(h1));
            __half l2 = __float2half_rn(f2 - __half2float(h2));
            __half l3 = __float2half_rn(f3 - __half2float(h3));
            int off = c*PADX + p4*4;
            *(__half2*)&xh[off]     = __halves2half2(h0, h1);
            *(__half2*)&xh[off + 2] = __halves2half2(h2, h3);
            *(__half2*)&xl[off]     = __halves2half2(l0, l1);
            *(__half2*)&xl[off + 2] = __halves2half2(l2, l3);
        }
        #pragma unroll
        for (int it = 0; it < 4; it++) {
            int idx = tid + it * 256;
            int o = idx >> 3, k4 = idx & 7;
            float4 v = wv[it];
            __half h0 = __float2half_rn(v.x), h1 = __float2half_rn(v.y);
            __half h2 = __float2half_rn(v.z), h3 = __float2half_rn(v.w);
            __half l0 = __float2half_rn(v.x - __half2float(h0));
            __half l1 = __float2half_rn(v.y - __half2float(h1));
            __half l2 = __float2half_rn(v.z - __half2float(h2));
            __half l3 = __float2half_rn(v.w - __half2float(h3));
            int off = o*PADK + k4*4;
            *(__half2*)&wh[off]     = __halves2half2(h0, h1);
            *(__half2*)&wh[off + 2] = __halves2half2(h2, h3);
            *(__half2*)&wl[off]     = __halves2half2(l0, l1);
            *(__half2*)&wl[off + 2] = __halves2half2(l2, l3);
        }
        __syncthreads();

        // ---- issue next slab's loads (overlap with MMAs below) ----
        int nc = cc + 32;
        if (nc < Cin) {
            #pragma unroll
            for (int it = 0; it < 4; it++) {
                int idx = tid + it * 256;
                int c = nc + (idx >> 5); int p4 = idx & 31;
                const float* src = (c < C0) ? (src0 + (size_t)(n*C0 + c) * hw)
                                            : (src1 + (size_t)(n*C1 + (c - C0)) * hw);
                xv[it] = *(const float4*)(src + hw0 + p4*4);
                sS[it] = g_S[c]; sT[it] = g_T[c];
            }
            #pragma unroll
            for (int it = 0; it < 4; it++) {
                int idx = tid + it * 256;
                int o = idx >> 3, k4 = idx & 7;
                int oc = ot*128 + o;
                if (oc < Cout) wv[it] = *(const float4*)(w + (size_t)oc * Cin + nc + k4*4);
                else { wv[it].x = 0.f; wv[it].y = 0.f; wv[it].z = 0.f; wv[it].w = 0.f; }
            }
        }

        // ---- MMAs on current slab ----
        #pragma unroll
        for (int kk = 0; kk < 32; kk += 16) {
            unsigned ah[4], al[4];
            {
                int m0 = wid*16;           // 0..112, rows in [0,128)
                const __half* pa = xh + (kk + (lane & 7) + ((lane >> 4) << 3))*PADX
                                      + m0 + (((lane >> 3) & 1) << 3);
                const __half* pb = xl + (kk + (lane & 7) + ((lane >> 4) << 3))*PADX
                                      + m0 + (((lane >> 3) & 1) << 3);
                ldm4t(ah[0], ah[1], ah[2], ah[3], pa);
                ldm4t(al[0], al[1], al[2], al[3], pb);
            }
            #pragma unroll
            for (int j = 0; j < 16; j++) {
                int bo = (j*8 + g)*PADK + kk + 2*t;
                unsigned bh0 = *(const unsigned*)(wh + bo);
                unsigned bh1 = *(const unsigned*)(wh + bo + 8);
                unsigned bl0 = *(const unsigned*)(wl + bo);
                unsigned bl1 = *(const unsigned*)(wl + bo + 8);
                mma16816(acc[j], ah[0], ah[1], ah[2], ah[3], bh0, bh1);
                mma16816(acc[j], ah[0], ah[1], ah[2], ah[3], bl0, bl1);
                mma16816(acc[j], al[0], al[1], al[2], al[3], bh0, bh1);
            }
        }
        __syncthreads();
    }

    // ---- writeback: C rows pr, pr+8 (px), cols j*8+2t (+1) (oc) ----
    {
        int pr = wid*16 + g;               // 0..127
        #pragma unroll
        for (int j = 0; j < 16; j++) {
            int o = ot*128 + j*8 + 2*t;
            if (o < Cout) {
                float bv = bias[o];
                float v0 = acc[j][0] + bv;
                float v2 = acc[j][2] + bv;
                if (relu) { v0 = fmaxf(v0, 0.f); v2 = fmaxf(v2, 0.f); }
                float* op = out + (size_t)(n*outStride + o) * hw + hw0;
                op[pr] = v0; op[pr + 8] = v2;
                if (mirror != 0 && o >= 64) {
                    float* mp = mirror + (size_t)(n*128 + (o - 64)) * hw + hw0;
                    mp[pr] = v0; mp[pr + 8] = v2;
                }
            }
            if (o + 1 < Cout) {
                float bv = bias[o+1];
                float v1 = acc[j][1] + bv;
                float v3 = acc[j][3] + bv;
                if (relu) { v1 = fmaxf(v1, 0.f); v3 = fmaxf(v3, 0.f); }
                float* op = out + (size_t)(n*outStride + o + 1) * hw + hw0;
                op[pr] = v1; op[pr + 8] = v3;
                if (mirror != 0 && o + 1 >= 64) {
                    float* mp = mirror + (size_t)(n*128 + (o + 1 - 64)) * hw + hw0;
                    mp[pr] = v1; mp[pr + 8] = v3;
                }
            }
        }
    }
}

// ---------------- align-corners bilinear resize ----------------
__global__ void resize_kernel(const float* __restrict__ src, float* __restrict__ dst,
                              int C, int Hs, int Ws, int Hd, int Wd) {
    int idx = blockIdx.x * blockDim.x + threadIdx.x;
    int total = NB * C * Hd * Wd;
    if (idx >= total) return;
    int x = idx % Wd; int y = (idx / Wd) % Hd; int nc = idx / (Wd * Hd);
    float sy = y * (float)(Hs - 1) / (float)(Hd - 1);
    float sx = x * (float)(Ws - 1) / (float)(Wd - 1);
    int y0 = (int)floorf(sy); int x0 = (int)floorf(sx);
    float wy = sy - y0, wx = sx - x0;
    int y1 = min(y0 + 1, Hs - 1), x1 = min(x0 + 1, Ws - 1);
    const float* p = src + (size_t)nc * Hs * Ws;
    float v00 = p[y0*Ws + x0], v01 = p[y0*Ws + x1];
    float v10 = p[y1*Ws + x0], v11 = p[y1*Ws + x1];
    float top = v00 + (v10 - v00) * wy;
    float bot = v01 + (v11 - v01) * wy;
    dst[idx] = top + (bot - top) * wx;
}

// ---------------- grid_sample (border) of temporal_kv ----------------
__global__ void warp_kernel(const float* __restrict__ temporal, const float* __restrict__ mv) {
    int p = blockIdx.x * blockDim.x + threadIdx.x;
    if (p >= NB * HW) return;
    int chunk = blockIdx.y;             // 0..15
    int n = p / HW; int hw = p % HW;
    int h = hw >> 8; int w = hw & 255;
    float xsv = -1.f + 2.f * w / (float)(WW - 1);
    float ysv = -1.f + 2.f * h / (float)(HH - 1);
    float gx = mv[(size_t)(n*2 + 0) * HW + hw] * (2.f / WW) + xsv;
    float gy = ysv - mv[(size_t)(n*2 + 1) * HW + hw] * (2.f / HH);
    float ix = fminf(fmaxf((gx + 1.f) * 0.5f * (WW - 1), 0.f), (float)(WW - 1));
    float iy = fminf(fmaxf((gy + 1.f) * 0.5f * (HH - 1), 0.f), (float)(HH - 1));
    int x0 = (int)floorf(ix), y0 = (int)floorf(iy);
    float wx = ix - x0, wy = iy - y0;
    int x1 = min(x0 + 1, WW - 1), y1 = min(y0 + 1, HH - 1);
    float w00 = (1.f-wy)*(1.f-wx), w01 = (1.f-wy)*wx, w10 = wy*(1.f-wx), w11 = wy*wx;
    int i00 = y0*WW + x0, i01 = y0*WW + x1, i10 = y1*WW + x0, i11 = y1*WW + x1;
    const float* base = temporal + (size_t)(n*128 + chunk*8) * HW;
    float* dst = &g_WARP[(size_t)(n*128 + chunk*8) * HW + hw];
    #pragma unroll
    for (int c = 0; c < 8; c++) {
        const float* pp = base + (size_t)c * HW;
        dst[(size_t)c * HW] = pp[i00]*w00 + pp[i01]*w01 + pp[i10]*w10 + pp[i11]*w11;
    }
}

// ---------------- copy ds_latent tail channels into g_DSS ----------------
__global__ void dscopy_kernel(const float* __restrict__ dsl) {
    int idx = blockIdx.x * blockDim.x + threadIdx.x;
    if (idx >= NB * 3 * DHW) return;
    int n = idx / (3 * DHW); int rem = idx % (3 * DHW);
    int c = rem / DHW; int i = rem % DHW;
    g_DSS[(size_t)(n*128 + 125 + c) * DHW + i] = dsl[(size_t)(n*96 + 93 + c) * DHW + i];
}

// ---------------- warp tree-reduce of (sum, sumsq) ----------------
__device__ __forceinline__ void warp_red2(float& s, float& q) {
    #pragma unroll
    for (int off = 16; off > 0; off >>= 1) {
        s += __shfl_xor_sync(0xffffffffu, s, off);
        q += __shfl_xor_sync(0xffffffffu, q, off);
    }
}

// ---------------- windowed attention: tensor-core fp16 QK/PV, warp-coop LN ----------------
__global__ __launch_bounds__(128)
void attn_kernel(const float* __restrict__ radiance,
                 const float* __restrict__ qg, const float* __restrict__ qb,
                 const float* __restrict__ kg, const float* __restrict__ kb,
                 const float* __restrict__ vg, const float* __restrict__ vb) {
    extern __shared__ char smraw[];
    __half* Qh = (__half*)smraw;           // 64 x PAD
    __half* Kh = Qh + 64*PAD;
    __half* Vh = Kh + 64*PAD;
    float* Raw0 = (float*)(Vh + 64*PAD);   // 64 x RSTR
    float* Raw1 = Raw0 + 64*RSTR;

    int tid = threadIdx.x;
    int lane = tid & 31;
    int w = tid >> 5;
    int n = blockIdx.x >> 10;
    int l = blockIdx.x & 1023;
    int by = (l >> 5) * 8, bx = (l & 31) * 8;
    int cch = 2*lane;

    #pragma unroll
    for (int it = 0; it < 8; it++) {
        int idx = tid + it * 128;
        int c = idx >> 4, q = idx & 15;
        int y = by + (q >> 1), x = bx + (q & 1)*4;
        int r0 = 4*q;
        float4 v = *(const float4*)&g_SU[(size_t)(n*189 + c) * HW + y*256 + x];
        Raw0[(r0  )*RSTR + c] = v.x;
        Raw0[(r0+1)*RSTR + c] = v.y;
        Raw0[(r0+2)*RSTR + c] = v.z;
        Raw0[(r0+3)*RSTR + c] = v.w;
    }
    __syncthreads();
    {
        float gq0 = qg[cch], gq1 = qg[cch+1], bq0 = qb[cch], bq1 = qb[cch+1];
        #pragma unroll
        for (int rr = 0; rr < 16; rr++) {
            int r = w*16 + rr;
            float2 v = *(const float2*)&Raw0[r*RSTR + cch];
            float s = v.x + v.y, q2 = v.x*v.x + v.y*v.y;
            warp_red2(s, q2);
            float mu = s * (1.f/64.f);
            float var = q2 * (1.f/64.f) - mu*mu;
            float rs = rsqrtf(var + 1e-5f);
            *(__half2*)&Qh[r*PAD + cch] = __floats2half2_rn(
                ((v.x - mu) * rs * gq0 + bq0) * 0.125f,
                ((v.y - mu) * rs * gq1 + bq1) * 0.125f);
        }
    }
    __syncthreads();

    unsigned qa[4][4];
    {
        int q0 = w * 16;
        #pragma unroll
        for (int kk = 0; kk < 4; kk++) {
            const __half* p = Qh + (q0 + (lane & 15))*PAD + kk*16 + ((lane >> 4) << 3);
            ldm4(qa[kk][0], qa[kk][1], qa[kk][2], qa[kk][3], p);
        }
    }

    float o[8][4];
    #pragma unroll
    for (int t = 0; t < 8; t++)
        #pragma unroll
        for (int j = 0; j < 4; j++) o[t][j] = 0.f;
    float m0 = -1e30f, m1 = -1e30f, l0 = 0.f, l1 = 0.f;

    float gk0 = kg[cch], gk1 = kg[cch+1], bk0 = kb[cch], bk1 = kb[cch+1];
    float gv0 = (cch   < 61) ? vg[cch]   : 0.f;
    float gv1 = (cch+1 < 61) ? vg[cch+1] : 0.f;
    float bv0 = (cch   < 61) ? vb[cch]   : 0.f;
    float bv1 = (cch+1 < 61) ? vb[cch+1] : 0.f;

    for (int ci = 0; ci < 6; ci++) {
        if (ci < 4) {
            #pragma unroll
            for (int it = 0; it < 8; it++) {
                int idx = tid + it * 128;
                int c = idx >> 4, q = idx & 15;
                int ky = ci*4 + (q >> 2), xq = q & 3;
                int y = by - 4 + ky, x = bx - 4 + xq*4;
                int r0 = (q >> 2)*16 + xq*4;
                float4 kv4, vv4;
                if (y >= 0 && y < 256 && x >= 0 && x < 256) {
                    int off = y*256 + x;
                    kv4 = *(const float4*)&g_SU[(size_t)(n*189 + 64 + c) * HW + off];
                    vv4 = (c < 61)
                        ? *(const float4*)&g_SU[(size_t)(n*189 + 128 + c) * HW + off]
                        : *(const float4*)&radiance[(size_t)(n*3 + c - 61) * HW + off];
                } else {
                    kv4.x = kv4.y = kv4.z = kv4.w = 0.f;
                    vv4.x = vv4.y = vv4.z = vv4.w = 0.f;
                }
                Raw0[(r0  )*RSTR + c] = kv4.x;  Raw1[(r0  )*RSTR + c] = vv4.x;
                Raw0[(r0+1)*RSTR + c] = kv4.y;  Raw1[(r0+1)*RSTR + c] = vv4.y;
                Raw0[(r0+2)*RSTR + c] = kv4.z;  Raw1[(r0+2)*RSTR + c] = vv4.z;
                Raw0[(r0+3)*RSTR + c] = kv4.w;  Raw1[(r0+3)*RSTR + c] = vv4.w;
            }
        } else {
            const float* src = (ci == 4) ? g_WARP : g_DSE;
            #pragma unroll
            for (int it = 0; it < 8; it++) {
                int idx = tid + it * 128;
                int c = idx >> 4, q = idx & 15;
                int y = by + (q >> 1), x = bx + (q & 1)*4;
                int r0 = 4*q;
                int off = y*256 + x;
                float4 kv4 = *(const float4*)&src[(size_t)(n*128 + c) * HW + off];
                float4 vv4 = *(const float4*)&src[(size_t)(n*128 + 64 + c) * HW + off];
                Raw0[(r0  )*RSTR + c] = kv4.x;  Raw1[(r0  )*RSTR + c] = vv4.x;
                Raw0[(r0+1)*RSTR + c] = kv4.y;  Raw1[(r0+1)*RSTR + c] = vv4.y;
                Raw0[(r0+2)*RSTR + c] = kv4.z;  Raw1[(r0+2)*RSTR + c] = vv4.z;
                Raw0[(r0+3)*RSTR + c] = kv4.w;  Raw1[(r0+3)*RSTR + c] = vv4.w;
            }
        }
        __syncthreads();

        #pragma unroll
        for (int rr = 0; rr < 16; rr++) {
            int r = w*16 + rr;
            float2 v = *(const float2*)&Raw0[r*RSTR + cch];
            float s = v.x + v.y, q2 = v.x*v.x + v.y*v.y;
            warp_red2(s, q2);
            float mu = s * (1.f/64.f);
            float var = q2 * (1.f/64.f) - mu*mu;
            float rs = rsqrtf(var + 1e-5f);
            *(__half2*)&Kh[r*PAD + cch] = __floats2half2_rn(
                (v.x - mu) * rs * gk0 + bk0,
                (v.y - mu) * rs * gk1 + bk1);
        }
        #pragma unroll
        for (int rr = 0; rr < 16; rr++) {
            int r = w*16 + rr;
            float2 v = *(const float2*)&Raw1[r*RSTR + cch];
            float e0 = (cch   < 61) ? v.x : 0.f;
            float e1 = (cch+1 < 61) ? v.y : 0.f;
            float s = e0 + e1, q2 = e0*e0 + e1*e1;
            warp_red2(s, q2);
            float mu = s * (1.f/61.f);
            float var = q2 * (1.f/61.f) - mu*mu;
            float rs = rsqrtf(var + 1e-5f);
            float o0 = (cch   < 61) ? (v.x - mu) * rs * gv0 + bv0 : v.x;
            float o1 = (cch+1 < 61) ? (v.y - mu) * rs * gv1 + bv1 : v.y;
            *(__half2*)&Vh[r*PAD + cch] = __floats2half2_rn(o0, o1);
        }
        __syncthreads();

        float s[8][4];
        #pragma unroll
        for (int t = 0; t < 8; t++)
            #pragma unroll
            for (int j = 0; j < 4; j++) s[t][j] = 0.f;
        #pragma unroll
        for (int kk = 0; kk < 4; kk++) {
            #pragma unroll
            for (int np = 0; np < 4; np++) {
                unsigned b0, b1, b2, b3;
                const __half* p = Kh + (np*16 + (lane & 7) + ((lane >> 4) << 3))*PAD
                                     + kk*16 + (((lane >> 3) & 1) << 3);
                ldm4(b0, b1, b2, b3, p);
                mma16816(s[2*np],   qa[kk][0], qa[kk][1], qa[kk][2], qa[kk][3], b0, b1);
                mma16816(s[2*np+1], qa[kk][0], qa[kk][1], qa[kk][2], qa[kk][3], b2, b3);
            }
        }

        float mx0 = -1e30f, mx1 = -1e30f;
        #pragma unroll
        for (int t = 0; t < 8; t++) {
            mx0 = fmaxf(mx0, fmaxf(s[t][0], s[t][1]));
            mx1 = fmaxf(mx1, fmaxf(s[t][2], s[t][3]));
        }
        mx0 = fmaxf(mx0, __shfl_xor_sync(0xffffffffu, mx0, 1));
        mx0 = fmaxf(mx0, __shfl_xor_sync(0xffffffffu, mx0, 2));
        mx1 = fmaxf(mx1, __shfl_xor_sync(0xffffffffu, mx1, 1));
        mx1 = fmaxf(mx1, __shfl_xor_sync(0xffffffffu, mx1, 2));
        float mn0 = fmaxf(m0, mx0), mn1 = fmaxf(m1, mx1);
        float corr0 = __expf(m0 - mn0), corr1 = __expf(m1 - mn1);
        m0 = mn0; m1 = mn1;
        float sum0 = 0.f, sum1 = 0.f;
        #pragma unroll
        for (int t = 0; t < 8; t++) {
            s[t][0] = __expf(s[t][0] - m0); s[t][1] = __expf(s[t][1] - m0);
            s[t][2] = __expf(s[t][2] - m1); s[t][3] = __expf(s[t][3] - m1);
            sum0 += s[t][0] + s[t][1];
            sum1 += s[t][2] + s[t][3];
        }
        sum0 += __shfl_xor_sync(0xffffffffu, sum0, 1);
        sum0 += __shfl_xor_sync(0xffffffffu, sum0, 2);
        sum1 += __shfl_xor_sync(0xffffffffu, sum1, 1);
        sum1 += __shfl_xor_sync(0xffffffffu, sum1, 2);
        l0 = l0 * corr0 + sum0;
        l1 = l1 * corr1 + sum1;
        #pragma unroll
        for (int t = 0; t < 8; t++) {
            o[t][0] *= corr0; o[t][1] *= corr0;
            o[t][2] *= corr1; o[t][3] *= corr1;
        }

        #pragma unroll
        for (int jp = 0; jp < 4; jp++) {
            unsigned a0 = packh2(s[2*jp][0],   s[2*jp][1]);
            unsigned a1 = packh2(s[2*jp][2],   s[2*jp][3]);
            unsigned a2 = packh2(s[2*jp+1][0], s[2*jp+1][1]);
            unsigned a3 = packh2(s[2*jp+1][2], s[2*jp+1][3]);
            #pragma unroll
            for (int np = 0; np < 4; np++) {
                unsigned b0, b1, b2, b3;
                const __half* p = Vh + (jp*16 + (lane & 7) + (((lane >> 3) & 1) << 3))*PAD
                                     + np*16 + ((lane >> 4) << 3);
                ldm4t(b0, b1, b2, b3, p);
                mma16816(o[2*np],   a0, a1, a2, a3, b0, b1);
                mma16816(o[2*np+1], a0, a1, a2, a3, b2, b3);
            }
        }
        __syncthreads();
    }

    float inv0 = 1.f / l0, inv1 = 1.f / l1;
    int r0 = w*16 + (lane >> 2);
    int r1 = r0 + 8;
    int y0 = by + (r0 >> 3), x0 = bx + (r0 & 7);
    int y1 = by + (r1 >> 3), x1 = bx + (r1 & 7);
    #pragma unroll
    for (int t = 0; t < 8; t++) {
        int c = t*8 + 2*(lane & 3);
        g_ATT[(size_t)(n*64 + c    ) * HW + y0*256 + x0] = o[t][0] * inv0;
        g_ATT[(size_t)(n*64 + c + 1) * HW + y0*256 + x0] = o[t][1] * inv0;
        g_ATT[(size_t)(n*64 + c    ) * HW + y1*256 + x1] = o[t][2] * inv1;
        g_ATT[(size_t)(n*64 + c + 1) * HW + y1*256 + x1] = o[t][3] * inv1;
    }
}

// ---------------- output tail: only the g_ATT-sourced channels (float4) ----------------
__global__ void tail_kernel(float* __restrict__ out) {
    int idx = blockIdx.x * blockDim.x + threadIdx.x;
    const int HW4 = HW / 4;
    if (idx >= NB * 3 * HW4) return;
    int n = idx / (3 * HW4); int rem = idx % (3 * HW4);
    int c = rem / HW4; int hw4 = rem % HW4;
    float4 v = *(const float4*)&g_ATT[(size_t)(n*64 + 61 + c) * HW + hw4*4];
    *(float4*)&out[(size_t)(n*64 + 61 + c) * HW + hw4*4] = v;
    *(float4*)&out[(size_t)NB*64*HW + (size_t)(n*128 + 125 + c) * HW + hw4*4] = v;
}

// ---------------- host launcher ----------------
extern "C" void kernel_launch(void* const* d_in, const int* in_sizes, int n_in,
                              void* d_out, int out_size) {
    const float* radiance = (const float*)d_in[0];
    const float* skip     = (const float*)d_in[1];
    const float* dsl      = (const float*)d_in[2];
    const float* temporal = (const float*)d_in[3];
    const float* mv       = (const float*)d_in[4];
    const float* su_bn_g  = (const float*)d_in[5];
    const float* su_bn_b  = (const float*)d_in[6];
    const float* su_w     = (const float*)d_in[7];
    const float* su_b     = (const float*)d_in[8];
    const float* ds_bn_g  = (const float*)d_in[9];
    const float* ds_bn_b  = (const float*)d_in[10];
    const float* ds_w     = (const float*)d_in[11];
    const float* ds_b     = (const float*)d_in[12];
    const float* qln_g    = (const float*)d_in[13];
    const float* qln_b    = (const float*)d_in[14];
    const float* kln_g    = (const float*)d_in[15];
    const float* kln_b    = (const float*)d_in[16];
    const float* vln_g    = (const float*)d_in[17];
    const float* vln_b    = (const float*)d_in[18];
    const float* f1_g     = (const float*)d_in[19];
    const float* f1_b     = (const float*)d_in[20];
    const float* w1       = (const float*)d_in[21];
    const float* b1       = (const float*)d_in[22];
    const float* f2_g     = (const float*)d_in[23];
    const float* f2_b     = (const float*)d_in[24];
    const float* w2       = (const float*)d_in[25];
    const float* b2       = (const float*)d_in[26];
    float* out = (float*)d_out;

    float *dUS, *dSU, *dDSS, *dDSE, *dATT, *dH1;
    cudaGetSymbolAddress((void**)&dUS,  g_US);
    cudaGetSymbolAddress((void**)&dSU,  g_SU);
    cudaGetSymbolAddress((void**)&dDSS, g_DSS);
    cudaGetSymbolAddress((void**)&dDSE, g_DSE);
    cudaGetSymbolAddress((void**)&dATT, g_ATT);
    cudaGetSymbolAddress((void**)&dH1,  g_H1);

    float* outTemporal = out + (size_t)NB*64*HW;

    const int ATTN_SMEM = 3*64*PAD*2 + 2*64*RSTR*4;   // 61440 B
    cudaFuncSetAttribute(attn_kernel, cudaFuncAttributeMaxDynamicSharedMemorySize, ATTN_SMEM);
    const int CONV_SMEM = 2*32*PADX*2 + 2*128*PADK*2; // 17408 + 20480 = 37888 B

    // 1. us = resize(ds_latent, 128->256)
    resize_kernel<<<(NB*96*HW + 255)/256, 256>>>(dsl, dUS, 96, 128, 128, 256, 256);
    // 2-3. su BN stats + conv1x1 -> su_emb (189 ch); ch 64..188 mirrored to temporal_out
    bn_stats1_kernel<<<dim3(192, NSLAB), 256>>>(skip, 96, dUS, 96, HW);
    bn_stats2_kernel<<<192, 32>>>(su_bn_g, su_bn_b, HW);
    conv1x1_tc_kernel<<<dim3((NB*HW)/128, 2), 256, CONV_SMEM>>>(skip, 96, dUS, 96, su_w, su_b, 189, HW, dSU, 189, 0, outTemporal);
    // 4. warped temporal kv
    warp_kernel<<<dim3((NB*HW + 255)/256, 16), 256>>>(temporal, mv);
    // 5-8. ds embedding
    bn_stats1_kernel<<<dim3(96, NSLAB), 256>>>(dsl, 96, (const float*)0, 0, DHW);
    bn_stats2_kernel<<<96, 32>>>(ds_bn_g, ds_bn_b, DHW);
    conv1x1_tc_kernel<<<dim3((NB*DHW)/128, 1), 256, CONV_SMEM>>>(dsl, 96, (const float*)0, 0, ds_w, ds_b, 125, DHW, dDSS, 128, 0, (float*)0);
    dscopy_kernel<<<(NB*3*DHW + 255)/256, 256>>>(dsl);
    resize_kernel<<<(NB*128*HW + 255)/256, 256>>>(dDSS, dDSE, 128, 128, 128, 256, 256);
    // 9. attention (tensor-core)
    attn_kernel<<<NB*1024, 128, ATTN_SMEM>>>(radiance, qln_g, qln_b, kln_g, kln_b, vln_g, vln_b);
    // 10-13. FFN
    bn_stats1_kernel<<<dim3(64, NSLAB), 256>>>(dATT, 64, (const float*)0, 0, HW);
    bn_stats2_kernel<<<64, 32>>>(f1_g, f1_b, HW);
    conv1x1_tc_kernel<<<dim3((NB*HW)/128, 1), 256, CONV_SMEM>>>(dATT, 64, (const float*)0, 0, w1, b1, 128, HW, dH1, 128, 1, (float*)0);
    bn_stats1_kernel<<<dim3(128, NSLAB), 256>>>(dH1, 128, (const float*)0, 0, HW);
    bn_stats2_kernel<<<128, 32>>>(f2_g, f2_b, HW);
    conv1x1_tc_kernel<<<dim3((NB*HW)/128, 1), 256, CONV_SMEM>>>(dH1, 128, (const float*)0, 0, w2, b2, 61, HW, out, 64, 0, (float*)0);
    // 14. remaining tail channels (attention-sourced)
    tail_kernel<<<(NB*3*HW/4 + 255)/256, 256>>>(out);
}

// round 13
// speedup vs baseline: 1.0285x; 1.0285x over previous
#include <cuda_runtime.h>
#include <cuda_fp16.h>
#include <math.h>

#define NB 2
#define HH 256
#define WW 256
#define HW 65536
#define DHW 16384   // 128*128
#define PAD 72      // fp16 row stride for ldmatrix tiles (attention)
#define RSTR 66     // attention raw fp32 row stride
#define NSLAB 16
#define PADX 264    // conv x smem row stride in halves ([k][px], 256 px + 8 pad)
#define PADK 40     // conv w smem row stride in halves ([oc][k])

// ---------------- scratch (static device allocations) ----------------
__device__ float g_US [NB*96 *HW];
__device__ float g_SU [NB*189*HW];
__device__ float g_WARP[NB*128*HW];
__device__ float g_DSS[NB*128*DHW];
__device__ float g_DSE[NB*128*HW];
__device__ float g_ATT[NB*64 *HW];
__device__ float g_H1 [NB*128*HW];
__device__ float g_S[192];
__device__ float g_T[192];
__device__ float g_PSUM[192*NSLAB];
__device__ float g_PSQ [192*NSLAB];

// ---------------- BN stats stage 1 ----------------
__global__ void bn_stats1_kernel(const float* __restrict__ src0, int C0,
                                 const float* __restrict__ src1, int C1,
                                 int hw) {
    int c = blockIdx.x;
    int slab = blockIdx.y;
    const float* base; int cs;
    if (c < C0) { base = src0 + (size_t)c * hw; cs = C0; }
    else        { base = src1 + (size_t)(c - C0) * hw; cs = C1; }
    int sl = hw / NSLAB;
    float sum = 0.f, sq = 0.f;
    for (int n = 0; n < NB; n++) {
        const float4* p = (const float4*)(base + (size_t)n * cs * hw + (size_t)slab * sl);
        int nv = sl >> 2;
        for (int i = threadIdx.x; i < nv; i += blockDim.x) {
            float4 v = p[i];
            sum += v.x + v.y + v.z + v.w;
            sq  += v.x*v.x + v.y*v.y + v.z*v.z + v.w*v.w;
        }
    }
    __shared__ float ssum[256], ssq[256];
    ssum[threadIdx.x] = sum; ssq[threadIdx.x] = sq; __syncthreads();
    for (int o = 128; o > 0; o >>= 1) {
        if (threadIdx.x < o) { ssum[threadIdx.x] += ssum[threadIdx.x+o]; ssq[threadIdx.x] += ssq[threadIdx.x+o]; }
        __syncthreads();
    }
    if (threadIdx.x == 0) {
        g_PSUM[c*NSLAB + slab] = ssum[0];
        g_PSQ [c*NSLAB + slab] = ssq[0];
    }
}

// ---------------- BN stats stage 2 ----------------
__global__ void bn_stats2_kernel(const float* __restrict__ g, const float* __restrict__ b,
                                 int hw) {
    int c = blockIdx.x;
    if (threadIdx.x == 0) {
        float sum = 0.f, sq = 0.f;
        #pragma unroll
        for (int s = 0; s < NSLAB; s++) { sum += g_PSUM[c*NSLAB + s]; sq += g_PSQ[c*NSLAB + s]; }
        float inv = 1.f / (float)(NB * hw);
        float m = sum * inv;
        float v = sq * inv - m * m;
        float s = g[c] * rsqrtf(v + 1e-5f);
        g_S[c] = s; g_T[c] = b[c] - m * s;
    }
}

// ---------------- mma helpers ----------------
__device__ __forceinline__ void ldm4(unsigned& r0, unsigned& r1, unsigned& r2, unsigned& r3,
                                     const __half* p) {
    unsigned a = (unsigned)__cvta_generic_to_shared(p);
    asm volatile("ldmatrix.sync.aligned.m8n8.x4.shared.b16 {%0,%1,%2,%3}, [%4];"
                 : "=r"(r0), "=r"(r1), "=r"(r2), "=r"(r3) : "r"(a));
}
__device__ __forceinline__ void ldm4t(unsigned& r0, unsigned& r1, unsigned& r2, unsigned& r3,
                                      const __half* p) {
    unsigned a = (unsigned)__cvta_generic_to_shared(p);
    asm volatile("ldmatrix.sync.aligned.m8n8.x4.trans.shared.b16 {%0,%1,%2,%3}, [%4];"
                 : "=r"(r0), "=r"(r1), "=r"(r2), "=r"(r3) : "r"(a));
}
__device__ __forceinline__ void mma16816(float* d, unsigned a0, unsigned a1, unsigned a2, unsigned a3,
                                         unsigned b0, unsigned b1) {
    asm volatile("mma.sync.aligned.m16n8k16.row.col.f32.f16.f16.f32 "
                 "{%0,%1,%2,%3}, {%4,%5,%6,%7}, {%8,%9}, {%0,%1,%2,%3};"
                 : "+f"(d[0]), "+f"(d[1]), "+f"(d[2]), "+f"(d[3])
                 : "r"(a0), "r"(a1), "r"(a2), "r"(a3), "r"(b0), "r"(b1));
}
__device__ __forceinline__ unsigned packh2(float lo, float hi) {
    __half2 h = __floats2half2_rn(lo, hi);
    return *(unsigned*)&h;
}

// ---------------- fused BN + conv1x1, tensor-core fp16 hi/lo split + reg double-buffer ----------------
// block tile: 256 px x 64 oc; 256 threads = 8 warps; warp = 32 px (2 m16 tiles) x 64 oc (R10 tile)
__global__ __launch_bounds__(256)
void conv1x1_tc_kernel(const float* __restrict__ src0, int C0,
                       const float* __restrict__ src1, int C1,
                       const float* __restrict__ w, const float* __restrict__ bias,
                       int Cout, int hw, float* __restrict__ out, int outStride, int relu,
                       float* __restrict__ mirror) {
    extern __shared__ char cvsm[];
    __half* xh = (__half*)cvsm;            // 32 x PADX halves
    __half* xl = xh + 32*PADX;
    __half* wh = xl + 32*PADX;             // 64 x PADK halves
    __half* wl = wh + 64*PADK;
    const int Cin = C0 + C1;
    int tid = threadIdx.x;
    int lane = tid & 31;
    int wid = tid >> 5;
    int g = lane >> 2, t = lane & 3;
    int p0 = blockIdx.x * 256;
    int n = p0 / hw, hw0 = p0 % hw;
    int ot = blockIdx.y;

    float acc[2][8][4];
    #pragma unroll
    for (int mt = 0; mt < 2; mt++)
        #pragma unroll
        for (int j = 0; j < 8; j++)
            #pragma unroll
            for (int e = 0; e < 4; e++) acc[mt][j][e] = 0.f;

    float4 xv[8];
    float4 wv[2];
    float  sS[8], sT[8];

    #pragma unroll
    for (int it = 0; it < 8; it++) {
        int idx = tid + it * 256;
        int c = idx >> 6, p4 = idx & 63;
        const float* src = (c < C0) ? (src0 + (size_t)(n*C0 + c) * hw)
                                    : (src1 + (size_t)(n*C1 + (c - C0)) * hw);
        xv[it] = *(const float4*)(src + hw0 + p4*4);
        sS[it] = g_S[c]; sT[it] = g_T[c];
    }
    #pragma unroll
    for (int it = 0; it < 2; it++) {
        int idx = tid + it * 256;
        int o = idx >> 3, k4 = idx & 7;
        int oc = ot*64 + o;
        if (oc < Cout) wv[it] = *(const float4*)(w + (size_t)oc * Cin + k4*4);
        else { wv[it].x = 0.f; wv[it].y = 0.f; wv[it].z = 0.f; wv[it].w = 0.f; }
    }

    for (int cc = 0; cc < Cin; cc += 32) {
        #pragma unroll
        for (int it = 0; it < 8; it++) {
            int idx = tid + it * 256;
            int c = idx >> 6, p4 = idx & 63;
            float s = sS[it], tt = sT[it];
            float f0 = xv[it].x*s + tt, f1 = xv[it].y*s + tt;
            float f2 = xv[it].z*s + tt, f3 = xv[it].w*s + tt;
            __half h0 = __float2half_rn(f0), h1 = __float2half_rn(f1);
            __half h2 = __float2half_rn(f2), h3 = __float2half_rn(f3);
            __half l0 = __float2half_rn(f0 - __half2float(h0));
            __half l1 = __float2half_rn(f1 - __half2float(h1));
            __half l2 = __float2half_rn(f2 - __half2float(h2));
            __half l3 = __float2half_rn(f3 - __half2float(h3));
            int off = c*PADX + p4*4;
            *(__half2*)&xh[off]     = __halves2half2(h0, h1);
            *(__half2*)&xh[off + 2] = __halves2half2(h2, h3);
            *(__half2*)&xl[off]     = __halves2half2(l0, l1);
            *(__half2*)&xl[off + 2] = __halves2half2(l2, l3);
        }
        #pragma unroll
        for (int it = 0; it < 2; it++) {
            int idx = tid + it * 256;
            int o = idx >> 3, k4 = idx & 7;
            float4 v = wv[it];
            __half h0 = __float2half_rn(v.x), h1 = __float2half_rn(v.y);
            __half h2 = __float2half_rn(v.z), h3 = __float2half_rn(v.w);
            __half l0 = __float2half_rn(v.x - __half2float(h0));
            __half l1 = __float2half_rn(v.y - __half2float(h1));
            __half l2 = __float2half_rn(v.z - __half2float(h2));
            __half l3 = __float2half_rn(v.w - __half2float(h3));
            int off = o*PADK + k4*4;
            *(__half2*)&wh[off]     = __halves2half2(h0, h1);
            *(__half2*)&wh[off + 2] = __halves2half2(h2, h3);
            *(__half2*)&wl[off]     = __halves2half2(l0, l1);
            *(__half2*)&wl[off + 2] = __halves2half2(l2, l3);
        }
        __syncthreads();

        int nc = cc + 32;
        if (nc < Cin) {
            #pragma unroll
            for (int it = 0; it < 8; it++) {
                int idx = tid + it * 256;
                int c = nc + (idx >> 6); int p4 = idx & 63;
                const float* src = (c < C0) ? (src0 + (size_t)(n*C0 + c) * hw)
                                            : (src1 + (size_t)(n*C1 + (c - C0)) * hw);
                xv[it] = *(const float4*)(src + hw0 + p4*4);
                sS[it] = g_S[c]; sT[it] = g_T[c];
            }
            #pragma unroll
            for (int it = 0; it < 2; it++) {
                int idx = tid + it * 256;
                int o = idx >> 3, k4 = idx & 7;
                int oc = ot*64 + o;
                if (oc < Cout) wv[it] = *(const float4*)(w + (size_t)oc * Cin + nc + k4*4);
                else { wv[it].x = 0.f; wv[it].y = 0.f; wv[it].z = 0.f; wv[it].w = 0.f; }
            }
        }

        #pragma unroll
        for (int kk = 0; kk < 32; kk += 16) {
            unsigned ah[2][4], al[2][4];
            #pragma unroll
            for (int mt = 0; mt < 2; mt++) {
                int m0 = wid*32 + mt*16;
                const __half* pa = xh + (kk + (lane & 7) + ((lane >> 4) << 3))*PADX
                                      + m0 + (((lane >> 3) & 1) << 3);
                const __half* pb = xl + (kk + (lane & 7) + ((lane >> 4) << 3))*PADX
                                      + m0 + (((lane >> 3) & 1) << 3);
                ldm4t(ah[mt][0], ah[mt][1], ah[mt][2], ah[mt][3], pa);
                ldm4t(al[mt][0], al[mt][1], al[mt][2], al[mt][3], pb);
            }
            #pragma unroll
            for (int j = 0; j < 8; j++) {
                int bo = (j*8 + g)*PADK + kk + 2*t;
                unsigned bh0 = *(const unsigned*)(wh + bo);
                unsigned bh1 = *(const unsigned*)(wh + bo + 8);
                unsigned bl0 = *(const unsigned*)(wl + bo);
                unsigned bl1 = *(const unsigned*)(wl + bo + 8);
                #pragma unroll
                for (int mt = 0; mt < 2; mt++) {
                    mma16816(acc[mt][j], ah[mt][0], ah[mt][1], ah[mt][2], ah[mt][3], bh0, bh1);
                    mma16816(acc[mt][j], ah[mt][0], ah[mt][1], ah[mt][2], ah[mt][3], bl0, bl1);
                    mma16816(acc[mt][j], al[mt][0], al[mt][1], al[mt][2], al[mt][3], bh0, bh1);
                }
            }
        }
        __syncthreads();
    }

    #pragma unroll
    for (int mt = 0; mt < 2; mt++) {
        int pr = wid*32 + mt*16 + g;
        #pragma unroll
        for (int j = 0; j < 8; j++) {
            int o = ot*64 + j*8 + 2*t;
            if (o < Cout) {
                float bv = bias[o];
                float v0 = acc[mt][j][0] + bv;
                float v2 = acc[mt][j][2] + bv;
                if (relu) { v0 = fmaxf(v0, 0.f); v2 = fmaxf(v2, 0.f); }
                float* op = out + (size_t)(n*outStride + o) * hw + hw0;
                op[pr] = v0; op[pr + 8] = v2;
                if (mirror != 0 && o >= 64) {
                    float* mp = mirror + (size_t)(n*128 + (o - 64)) * hw + hw0;
                    mp[pr] = v0; mp[pr + 8] = v2;
                }
            }
            if (o + 1 < Cout) {
                float bv = bias[o+1];
                float v1 = acc[mt][j][1] + bv;
                float v3 = acc[mt][j][3] + bv;
                if (relu) { v1 = fmaxf(v1, 0.f); v3 = fmaxf(v3, 0.f); }
                float* op = out + (size_t)(n*outStride + o + 1) * hw + hw0;
                op[pr] = v1; op[pr + 8] = v3;
                if (mirror != 0 && o + 1 >= 64) {
                    float* mp = mirror + (size_t)(n*128 + (o + 1 - 64)) * hw + hw0;
                    mp[pr] = v1; mp[pr + 8] = v3;
                }
            }
        }
    }
}

// ---------------- align-corners bilinear resize ----------------
__global__ void resize_kernel(const float* __restrict__ src, float* __restrict__ dst,
                              int C, int Hs, int Ws, int Hd, int Wd) {
    int idx = blockIdx.x * blockDim.x + threadIdx.x;
    int total = NB * C * Hd * Wd;
    if (idx >= total) return;
    int x = idx % Wd; int y = (idx / Wd) % Hd; int nc = idx / (Wd * Hd);
    float sy = y * (float)(Hs - 1) / (float)(Hd - 1);
    float sx = x * (float)(Ws - 1) / (float)(Wd - 1);
    int y0 = (int)floorf(sy); int x0 = (int)floorf(sx);
    float wy = sy - y0, wx = sx - x0;
    int y1 = min(y0 + 1, Hs - 1), x1 = min(x0 + 1, Ws - 1);
    const float* p = src + (size_t)nc * Hs * Ws;
    float v00 = p[y0*Ws + x0], v01 = p[y0*Ws + x1];
    float v10 = p[y1*Ws + x0], v11 = p[y1*Ws + x1];
    float top = v00 + (v10 - v00) * wy;
    float bot = v01 + (v11 - v01) * wy;
    dst[idx] = top + (bot - top) * wx;
}

// ---------------- grid_sample (border) of temporal_kv ----------------
__global__ void warp_kernel(const float* __restrict__ temporal, const float* __restrict__ mv) {
    int p = blockIdx.x * blockDim.x + threadIdx.x;
    if (p >= NB * HW) return;
    int chunk = blockIdx.y;             // 0..15
    int n = p / HW; int hw = p % HW;
    int h = hw >> 8; int w = hw & 255;
    float xsv = -1.f + 2.f * w / (float)(WW - 1);
    float ysv = -1.f + 2.f * h / (float)(HH - 1);
    float gx = mv[(size_t)(n*2 + 0) * HW + hw] * (2.f / WW) + xsv;
    float gy = ysv - mv[(size_t)(n*2 + 1) * HW + hw] * (2.f / HH);
    float ix = fminf(fmaxf((gx + 1.f) * 0.5f * (WW - 1), 0.f), (float)(WW - 1));
    float iy = fminf(fmaxf((gy + 1.f) * 0.5f * (HH - 1), 0.f), (float)(HH - 1));
    int x0 = (int)floorf(ix), y0 = (int)floorf(iy);
    float wx = ix - x0, wy = iy - y0;
    int x1 = min(x0 + 1, WW - 1), y1 = min(y0 + 1, HH - 1);
    float w00 = (1.f-wy)*(1.f-wx), w01 = (1.f-wy)*wx, w10 = wy*(1.f-wx), w11 = wy*wx;
    int i00 = y0*WW + x0, i01 = y0*WW + x1, i10 = y1*WW + x0, i11 = y1*WW + x1;
    const float* base = temporal + (size_t)(n*128 + chunk*8) * HW;
    float* dst = &g_WARP[(size_t)(n*128 + chunk*8) * HW + hw];
    #pragma unroll
    for (int c = 0; c < 8; c++) {
        const float* pp = base + (size_t)c * HW;
        dst[(size_t)c * HW] = pp[i00]*w00 + pp[i01]*w01 + pp[i10]*w10 + pp[i11]*w11;
    }
}

// ---------------- copy ds_latent tail channels into g_DSS ----------------
__global__ void dscopy_kernel(const float* __restrict__ dsl) {
    int idx = blockIdx.x * blockDim.x + threadIdx.x;
    if (idx >= NB * 3 * DHW) return;
    int n = idx / (3 * DHW); int rem = idx % (3 * DHW);
    int c = rem / DHW; int i = rem % DHW;
    g_DSS[(size_t)(n*128 + 125 + c) * DHW + i] = dsl[(size_t)(n*96 + 93 + c) * DHW + i];
}

// ---------------- warp tree-reduce of (sum, sumsq) ----------------
__device__ __forceinline__ void warp_red2(float& s, float& q) {
    #pragma unroll
    for (int off = 16; off > 0; off >>= 1) {
        s += __shfl_xor_sync(0xffffffffu, s, off);
        q += __shfl_xor_sync(0xffffffffu, q, off);
    }
}

// ---------------- windowed attention: tensor-core fp16 QK/PV, warp-coop LN ----------------
// single Raw buffer (44.5 KB total smem) -> higher occupancy; K and V staged in two passes
__global__ __launch_bounds__(128)
void attn_kernel(const float* __restrict__ radiance,
                 const float* __restrict__ qg, const float* __restrict__ qb,
                 const float* __restrict__ kg, const float* __restrict__ kb,
                 const float* __restrict__ vg, const float* __restrict__ vb) {
    extern __shared__ char smraw[];
    __half* Qh = (__half*)smraw;           // 64 x PAD
    __half* Kh = Qh + 64*PAD;
    __half* Vh = Kh + 64*PAD;
    float* Raw = (float*)(Vh + 64*PAD);    // 64 x RSTR (single buffer)

    int tid = threadIdx.x;
    int lane = tid & 31;
    int w = tid >> 5;
    int n = blockIdx.x >> 10;
    int l = blockIdx.x & 1023;
    int by = (l >> 5) * 8, bx = (l & 31) * 8;
    int cch = 2*lane;

    // ---- gather Q ----
    #pragma unroll
    for (int it = 0; it < 8; it++) {
        int idx = tid + it * 128;
        int c = idx >> 4, q = idx & 15;
        int y = by + (q >> 1), x = bx + (q & 1)*4;
        int r0 = 4*q;
        float4 v = *(const float4*)&g_SU[(size_t)(n*189 + c) * HW + y*256 + x];
        Raw[(r0  )*RSTR + c] = v.x;
        Raw[(r0+1)*RSTR + c] = v.y;
        Raw[(r0+2)*RSTR + c] = v.z;
        Raw[(r0+3)*RSTR + c] = v.w;
    }
    __syncthreads();
    {
        float gq0 = qg[cch], gq1 = qg[cch+1], bq0 = qb[cch], bq1 = qb[cch+1];
        #pragma unroll
        for (int rr = 0; rr < 16; rr++) {
            int r = w*16 + rr;
            float2 v = *(const float2*)&Raw[r*RSTR + cch];
            float s = v.x + v.y, q2 = v.x*v.x + v.y*v.y;
            warp_red2(s, q2);
            float mu = s * (1.f/64.f);
            float var = q2 * (1.f/64.f) - mu*mu;
            float rs = rsqrtf(var + 1e-5f);
            *(__half2*)&Qh[r*PAD + cch] = __floats2half2_rn(
                ((v.x - mu) * rs * gq0 + bq0) * 0.125f,
                ((v.y - mu) * rs * gq1 + bq1) * 0.125f);
        }
    }
    __syncthreads();

    unsigned qa[4][4];
    {
        int q0 = w * 16;
        #pragma unroll
        for (int kk = 0; kk < 4; kk++) {
            const __half* p = Qh + (q0 + (lane & 15))*PAD + kk*16 + ((lane >> 4) << 3);
            ldm4(qa[kk][0], qa[kk][1], qa[kk][2], qa[kk][3], p);
        }
    }

    float o[8][4];
    #pragma unroll
    for (int t = 0; t < 8; t++)
        #pragma unroll
        for (int j = 0; j < 4; j++) o[t][j] = 0.f;
    float m0 = -1e30f, m1 = -1e30f, l0 = 0.f, l1 = 0.f;

    float gk0 = kg[cch], gk1 = kg[cch+1], bk0 = kb[cch], bk1 = kb[cch+1];
    float gv0 = (cch   < 61) ? vg[cch]   : 0.f;
    float gv1 = (cch+1 < 61) ? vg[cch+1] : 0.f;
    float bv0 = (cch   < 61) ? vb[cch]   : 0.f;
    float bv1 = (cch+1 < 61) ? vb[cch+1] : 0.f;

    for (int ci = 0; ci < 6; ci++) {
        // ======== K pass ========
        if (ci < 4) {
            #pragma unroll
            for (int it = 0; it < 8; it++) {
                int idx = tid + it * 128;
                int c = idx >> 4, q = idx & 15;
                int ky = ci*4 + (q >> 2), xq = q & 3;
                int y = by - 4 + ky, x = bx - 4 + xq*4;
                int r0 = (q >> 2)*16 + xq*4;
                float4 kv4;
                if (y >= 0 && y < 256 && x >= 0 && x < 256) {
                    kv4 = *(const float4*)&g_SU[(size_t)(n*189 + 64 + c) * HW + y*256 + x];
                } else { kv4.x = kv4.y = kv4.z = kv4.w = 0.f; }
                Raw[(r0  )*RSTR + c] = kv4.x;
                Raw[(r0+1)*RSTR + c] = kv4.y;
                Raw[(r0+2)*RSTR + c] = kv4.z;
                Raw[(r0+3)*RSTR + c] = kv4.w;
            }
        } else {
            const float* src = (ci == 4) ? g_WARP : g_DSE;
            #pragma unroll
            for (int it = 0; it < 8; it++) {
                int idx = tid + it * 128;
                int c = idx >> 4, q = idx & 15;
                int y = by + (q >> 1), x = bx + (q & 1)*4;
                int r0 = 4*q;
                float4 kv4 = *(const float4*)&src[(size_t)(n*128 + c) * HW + y*256 + x];
                Raw[(r0  )*RSTR + c] = kv4.x;
                Raw[(r0+1)*RSTR + c] = kv4.y;
                Raw[(r0+2)*RSTR + c] = kv4.z;
                Raw[(r0+3)*RSTR + c] = kv4.w;
            }
        }
        __syncthreads();
        #pragma unroll
        for (int rr = 0; rr < 16; rr++) {
            int r = w*16 + rr;
            float2 v = *(const float2*)&Raw[r*RSTR + cch];
            float s = v.x + v.y, q2 = v.x*v.x + v.y*v.y;
            warp_red2(s, q2);
            float mu = s * (1.f/64.f);
            float var = q2 * (1.f/64.f) - mu*mu;
            float rs = rsqrtf(var + 1e-5f);
            *(__half2*)&Kh[r*PAD + cch] = __floats2half2_rn(
                (v.x - mu) * rs * gk0 + bk0,
                (v.y - mu) * rs * gk1 + bk1);
        }
        __syncthreads();

        // ======== V pass ========
        if (ci < 4) {
            #pragma unroll
            for (int it = 0; it < 8; it++) {
                int idx = tid + it * 128;
                int c = idx >> 4, q = idx & 15;
                int ky = ci*4 + (q >> 2), xq = q & 3;
                int y = by - 4 + ky, x = bx - 4 + xq*4;
                int r0 = (q >> 2)*16 + xq*4;
                float4 vv4;
                if (y >= 0 && y < 256 && x >= 0 && x < 256) {
                    int off = y*256 + x;
                    vv4 = (c < 61)
                        ? *(const float4*)&g_SU[(size_t)(n*189 + 128 + c) * HW + off]
                        : *(const float4*)&radiance[(size_t)(n*3 + c - 61) * HW + off];
                } else { vv4.x = vv4.y = vv4.z = vv4.w = 0.f; }
                Raw[(r0  )*RSTR + c] = vv4.x;
                Raw[(r0+1)*RSTR + c] = vv4.y;
                Raw[(r0+2)*RSTR + c] = vv4.z;
                Raw[(r0+3)*RSTR + c] = vv4.w;
            }
        } else {
            const float* src = (ci == 4) ? g_WARP : g_DSE;
            #pragma unroll
            for (int it = 0; it < 8; it++) {
                int idx = tid + it * 128;
                int c = idx >> 4, q = idx & 15;
                int y = by + (q >> 1), x = bx + (q & 1)*4;
                int r0 = 4*q;
                float4 vv4 = *(const float4*)&src[(size_t)(n*128 + 64 + c) * HW + y*256 + x];
                Raw[(r0  )*RSTR + c] = vv4.x;
                Raw[(r0+1)*RSTR + c] = vv4.y;
                Raw[(r0+2)*RSTR + c] = vv4.z;
                Raw[(r0+3)*RSTR + c] = vv4.w;
            }
        }
        __syncthreads();
        #pragma unroll
        for (int rr = 0; rr < 16; rr++) {
            int r = w*16 + rr;
            float2 v = *(const float2*)&Raw[r*RSTR + cch];
            float e0 = (cch   < 61) ? v.x : 0.f;
            float e1 = (cch+1 < 61) ? v.y : 0.f;
            float s = e0 + e1, q2 = e0*e0 + e1*e1;
            warp_red2(s, q2);
            float mu = s * (1.f/61.f);
            float var = q2 * (1.f/61.f) - mu*mu;
            float rs = rsqrtf(var + 1e-5f);
            float o0 = (cch   < 61) ? (v.x - mu) * rs * gv0 + bv0 : v.x;
            float o1 = (cch+1 < 61) ? (v.y - mu) * rs * gv1 + bv1 : v.y;
            *(__half2*)&Vh[r*PAD + cch] = __floats2half2_rn(o0, o1);
        }
        __syncthreads();

        // ======== MMAs ========
        float s[8][4];
        #pragma unroll
        for (int t = 0; t < 8; t++)
            #pragma unroll
            for (int j = 0; j < 4; j++) s[t][j] = 0.f;
        #pragma unroll
        for (int kk = 0; kk < 4; kk++) {
            #pragma unroll
            for (int np = 0; np < 4; np++) {
                unsigned b0, b1, b2, b3;
                const __half* p = Kh + (np*16 + (lane & 7) + ((lane >> 4) << 3))*PAD
                                     + kk*16 + (((lane >> 3) & 1) << 3);
                ldm4(b0, b1, b2, b3, p);
                mma16816(s[2*np],   qa[kk][0], qa[kk][1], qa[kk][2], qa[kk][3], b0, b1);
                mma16816(s[2*np+1], qa[kk][0], qa[kk][1], qa[kk][2], qa[kk][3], b2, b3);
            }
        }

        float mx0 = -1e30f, mx1 = -1e30f;
        #pragma unroll
        for (int t = 0; t < 8; t++) {
            mx0 = fmaxf(mx0, fmaxf(s[t][0], s[t][1]));
            mx1 = fmaxf(mx1, fmaxf(s[t][2], s[t][3]));
        }
        mx0 = fmaxf(mx0, __shfl_xor_sync(0xffffffffu, mx0, 1));
        mx0 = fmaxf(mx0, __shfl_xor_sync(0xffffffffu, mx0, 2));
        mx1 = fmaxf(mx1, __shfl_xor_sync(0xffffffffu, mx1, 1));
        mx1 = fmaxf(mx1, __shfl_xor_sync(0xffffffffu, mx1, 2));
        float mn0 = fmaxf(m0, mx0), mn1 = fmaxf(m1, mx1);
        float corr0 = __expf(m0 - mn0), corr1 = __expf(m1 - mn1);
        m0 = mn0; m1 = mn1;
        float sum0 = 0.f, sum1 = 0.f;
        #pragma unroll
        for (int t = 0; t < 8; t++) {
            s[t][0] = __expf(s[t][0] - m0); s[t][1] = __expf(s[t][1] - m0);
            s[t][2] = __expf(s[t][2] - m1); s[t][3] = __expf(s[t][3] - m1);
            sum0 += s[t][0] + s[t][1];
            sum1 += s[t][2] + s[t][3];
        }
        sum0 += __shfl_xor_sync(0xffffffffu, sum0, 1);
        sum0 += __shfl_xor_sync(0xffffffffu, sum0, 2);
        sum1 += __shfl_xor_sync(0xffffffffu, sum1, 1);
        sum1 += __shfl_xor_sync(0xffffffffu, sum1, 2);
        l0 = l0 * corr0 + sum0;
        l1 = l1 * corr1 + sum1;
        #pragma unroll
        for (int t = 0; t < 8; t++) {
            o[t][0] *= corr0; o[t][1] *= corr0;
            o[t][2] *= corr1; o[t][3] *= corr1;
        }

        #pragma unroll
        for (int jp = 0; jp < 4; jp++) {
            unsigned a0 = packh2(s[2*jp][0],   s[2*jp][1]);
            unsigned a1 = packh2(s[2*jp][2],   s[2*jp][3]);
            unsigned a2 = packh2(s[2*jp+1][0], s[2*jp+1][1]);
            unsigned a3 = packh2(s[2*jp+1][2], s[2*jp+1][3]);
            #pragma unroll
            for (int np = 0; np < 4; np++) {
                unsigned b0, b1, b2, b3;
                const __half* p = Vh + (jp*16 + (lane & 7) + (((lane >> 3) & 1) << 3))*PAD
                                     + np*16 + ((lane >> 4) << 3);
                ldm4t(b0, b1, b2, b3, p);
                mma16816(o[2*np],   a0, a1, a2, a3, b0, b1);
                mma16816(o[2*np+1], a0, a1, a2, a3, b2, b3);
            }
        }
        __syncthreads();
    }

    float inv0 = 1.f / l0, inv1 = 1.f / l1;
    int r0 = w*16 + (lane >> 2);
    int r1 = r0 + 8;
    int y0 = by + (r0 >> 3), x0 = bx + (r0 & 7);
    int y1 = by + (r1 >> 3), x1 = bx + (r1 & 7);
    #pragma unroll
    for (int t = 0; t < 8; t++) {
        int c = t*8 + 2*(lane & 3);
        g_ATT[(size_t)(n*64 + c    ) * HW + y0*256 + x0] = o[t][0] * inv0;
        g_ATT[(size_t)(n*64 + c + 1) * HW + y0*256 + x0] = o[t][1] * inv0;
        g_ATT[(size_t)(n*64 + c    ) * HW + y1*256 + x1] = o[t][2] * inv1;
        g_ATT[(size_t)(n*64 + c + 1) * HW + y1*256 + x1] = o[t][3] * inv1;
    }
}

// ---------------- output tail: only the g_ATT-sourced channels (float4) ----------------
__global__ void tail_kernel(float* __restrict__ out) {
    int idx = blockIdx.x * blockDim.x + threadIdx.x;
    const int HW4 = HW / 4;
    if (idx >= NB * 3 * HW4) return;
    int n = idx / (3 * HW4); int rem = idx % (3 * HW4);
    int c = rem / HW4; int hw4 = rem % HW4;
    float4 v = *(const float4*)&g_ATT[(size_t)(n*64 + 61 + c) * HW + hw4*4];
    *(float4*)&out[(size_t)(n*64 + 61 + c) * HW + hw4*4] = v;
    *(float4*)&out[(size_t)NB*64*HW + (size_t)(n*128 + 125 + c) * HW + hw4*4] = v;
}

// ---------------- host launcher ----------------
extern "C" void kernel_launch(void* const* d_in, const int* in_sizes, int n_in,
                              void* d_out, int out_size) {
    const float* radiance = (const float*)d_in[0];
    const float* skip     = (const float*)d_in[1];
    const float* dsl      = (const float*)d_in[2];
    const float* temporal = (const float*)d_in[3];
    const float* mv       = (const float*)d_in[4];
    const float* su_bn_g  = (const float*)d_in[5];
    const float* su_bn_b  = (const float*)d_in[6];
    const float* su_w     = (const float*)d_in[7];
    const float* su_b     = (const float*)d_in[8];
    const float* ds_bn_g  = (const float*)d_in[9];
    const float* ds_bn_b  = (const float*)d_in[10];
    const float* ds_w     = (const float*)d_in[11];
    const float* ds_b     = (const float*)d_in[12];
    const float* qln_g    = (const float*)d_in[13];
    const float* qln_b    = (const float*)d_in[14];
    const float* kln_g    = (const float*)d_in[15];
    const float* kln_b    = (const float*)d_in[16];
    const float* vln_g    = (const float*)d_in[17];
    const float* vln_b    = (const float*)d_in[18];
    const float* f1_g     = (const float*)d_in[19];
    const float* f1_b     = (const float*)d_in[20];
    const float* w1       = (const float*)d_in[21];
    const float* b1       = (const float*)d_in[22];
    const float* f2_g     = (const float*)d_in[23];
    const float* f2_b     = (const float*)d_in[24];
    const float* w2       = (const float*)d_in[25];
    const float* b2       = (const float*)d_in[26];
    float* out = (float*)d_out;

    float *dUS, *dSU, *dDSS, *dDSE, *dATT, *dH1;
    cudaGetSymbolAddress((void**)&dUS,  g_US);
    cudaGetSymbolAddress((void**)&dSU,  g_SU);
    cudaGetSymbolAddress((void**)&dDSS, g_DSS);
    cudaGetSymbolAddress((void**)&dDSE, g_DSE);
    cudaGetSymbolAddress((void**)&dATT, g_ATT);
    cudaGetSymbolAddress((void**)&dH1,  g_H1);

    float* outTemporal = out + (size_t)NB*64*HW;

    const int ATTN_SMEM = 3*64*PAD*2 + 64*RSTR*4;   // 27648 + 16896 = 44544 B
    cudaFuncSetAttribute(attn_kernel, cudaFuncAttributeMaxDynamicSharedMemorySize, ATTN_SMEM);
    const int CONV_SMEM = (2*32*PADX + 2*64*PADK) * 2;  // 44032 B

    // 1. us = resize(ds_latent, 128->256)
    resize_kernel<<<(NB*96*HW + 255)/256, 256>>>(dsl, dUS, 96, 128, 128, 256, 256);
    // 2-3. su BN stats + conv1x1 -> su_emb (189 ch); ch 64..188 mirrored to temporal_out
    bn_stats1_kernel<<<dim3(192, NSLAB), 256>>>(skip, 96, dUS, 96, HW);
    bn_stats2_kernel<<<192, 32>>>(su_bn_g, su_bn_b, HW);
    conv1x1_tc_kernel<<<dim3((NB*HW)/256, 3), 256, CONV_SMEM>>>(skip, 96, dUS, 96, su_w, su_b, 189, HW, dSU, 189, 0, outTemporal);
    // 4. warped temporal kv
    warp_kernel<<<dim3((NB*HW + 255)/256, 16), 256>>>(temporal, mv);
    // 5-8. ds embedding
    bn_stats1_kernel<<<dim3(96, NSLAB), 256>>>(dsl, 96, (const float*)0, 0, DHW);
    bn_stats2_kernel<<<96, 32>>>(ds_bn_g, ds_bn_b, DHW);
    conv1x1_tc_kernel<<<dim3((NB*DHW)/256, 2), 256, CONV_SMEM>>>(dsl, 96, (const float*)0, 0, ds_w, ds_b, 125, DHW, dDSS, 128, 0, (float*)0);
    dscopy_kernel<<<(NB*3*DHW + 255)/256, 256>>>(dsl);
    resize_kernel<<<(NB*128*HW + 255)/256, 256>>>(dDSS, dDSE, 128, 128, 128, 256, 256);
    // 9. attention (tensor-core)
    attn_kernel<<<NB*1024, 128, ATTN_SMEM>>>(radiance, qln_g, qln_b, kln_g, kln_b, vln_g, vln_b);
    // 10-13. FFN
    bn_stats1_kernel<<<dim3(64, NSLAB), 256>>>(dATT, 64, (const float*)0, 0, HW);
    bn_stats2_kernel<<<64, 32>>>(f1_g, f1_b, HW);
    conv1x1_tc_kernel<<<dim3((NB*HW)/256, 2), 256, CONV_SMEM>>>(dATT, 64, (const float*)0, 0, w1, b1, 128, HW, dH1, 128, 1, (float*)0);
    bn_stats1_kernel<<<dim3(128, NSLAB), 256>>>(dH1, 128, (const float*)0, 0, HW);
    bn_stats2_kernel<<<128, 32>>>(f2_g, f2_b, HW);
    conv1x1_tc_kernel<<<dim3((NB*HW)/256, 1), 256, CONV_SMEM>>>(dH1, 128, (const float*)0, 0, w2, b2, 61, HW, out, 64, 0, (float*)0);
    // 14. remaining tail channels (attention-sourced)
    tail_kernel<<<(NB*3*HW/4 + 255)/256, 256>>>(out);
}

// round 14
// speedup vs baseline: 1.0507x; 1.0215x over previous
#include <cuda_runtime.h>
#include <cuda_fp16.h>
#include <math.h>

#define NB 2
#define HH 256
#define WW 256
#define HW 65536
#define DHW 16384   // 128*128
#define PAD 72      // fp16 row stride for ldmatrix tiles (attention)
#define RSTR 66     // attention raw fp32 row stride
#define NSLAB 16
#define PADX 264    // conv x smem row stride in halves ([k][px], 256 px + 8 pad)
#define PADK 40     // conv w smem row stride in halves ([oc][k])

// ---------------- scratch (static device allocations) ----------------
__device__ float g_US [NB*96 *HW];
__device__ float g_SU [NB*189*HW];
__device__ float g_WARP[NB*128*HW];
__device__ float g_DSS[NB*128*DHW];
__device__ float g_DSE[NB*128*HW];
__device__ float g_ATT[NB*64 *HW];
__device__ float g_H1 [NB*128*HW];
__device__ float g_S[192];
__device__ float g_T[192];
__device__ float g_PSUM[192*NSLAB];
__device__ float g_PSQ [192*NSLAB];

// ---------------- BN stats stage 1 ----------------
__global__ void bn_stats1_kernel(const float* __restrict__ src0, int C0,
                                 const float* __restrict__ src1, int C1,
                                 int hw) {
    int c = blockIdx.x;
    int slab = blockIdx.y;
    const float* base; int cs;
    if (c < C0) { base = src0 + (size_t)c * hw; cs = C0; }
    else        { base = src1 + (size_t)(c - C0) * hw; cs = C1; }
    int sl = hw / NSLAB;
    float sum = 0.f, sq = 0.f;
    for (int n = 0; n < NB; n++) {
        const float4* p = (const float4*)(base + (size_t)n * cs * hw + (size_t)slab * sl);
        int nv = sl >> 2;
        for (int i = threadIdx.x; i < nv; i += blockDim.x) {
            float4 v = p[i];
            sum += v.x + v.y + v.z + v.w;
            sq  += v.x*v.x + v.y*v.y + v.z*v.z + v.w*v.w;
        }
    }
    __shared__ float ssum[256], ssq[256];
    ssum[threadIdx.x] = sum; ssq[threadIdx.x] = sq; __syncthreads();
    for (int o = 128; o > 0; o >>= 1) {
        if (threadIdx.x < o) { ssum[threadIdx.x] += ssum[threadIdx.x+o]; ssq[threadIdx.x] += ssq[threadIdx.x+o]; }
        __syncthreads();
    }
    if (threadIdx.x == 0) {
        g_PSUM[c*NSLAB + slab] = ssum[0];
        g_PSQ [c*NSLAB + slab] = ssq[0];
    }
}

// ---------------- BN stats stage 2 ----------------
__global__ void bn_stats2_kernel(const float* __restrict__ g, const float* __restrict__ b,
                                 int hw) {
    int c = blockIdx.x;
    if (threadIdx.x == 0) {
        float sum = 0.f, sq = 0.f;
        #pragma unroll
        for (int s = 0; s < NSLAB; s++) { sum += g_PSUM[c*NSLAB + s]; sq += g_PSQ[c*NSLAB + s]; }
        float inv = 1.f / (float)(NB * hw);
        float m = sum * inv;
        float v = sq * inv - m * m;
        float s = g[c] * rsqrtf(v + 1e-5f);
        g_S[c] = s; g_T[c] = b[c] - m * s;
    }
}

// ---------------- mma helpers ----------------
__device__ __forceinline__ void ldm4(unsigned& r0, unsigned& r1, unsigned& r2, unsigned& r3,
                                     const __half* p) {
    unsigned a = (unsigned)__cvta_generic_to_shared(p);
    asm volatile("ldmatrix.sync.aligned.m8n8.x4.shared.b16 {%0,%1,%2,%3}, [%4];"
                 : "=r"(r0), "=r"(r1), "=r"(r2), "=r"(r3) : "r"(a));
}
__device__ __forceinline__ void ldm4t(unsigned& r0, unsigned& r1, unsigned& r2, unsigned& r3,
                                      const __half* p) {
    unsigned a = (unsigned)__cvta_generic_to_shared(p);
    asm volatile("ldmatrix.sync.aligned.m8n8.x4.trans.shared.b16 {%0,%1,%2,%3}, [%4];"
                 : "=r"(r0), "=r"(r1), "=r"(r2), "=r"(r3) : "r"(a));
}
__device__ __forceinline__ void mma16816(float* d, unsigned a0, unsigned a1, unsigned a2, unsigned a3,
                                         unsigned b0, unsigned b1) {
    asm volatile("mma.sync.aligned.m16n8k16.row.col.f32.f16.f16.f32 "
                 "{%0,%1,%2,%3}, {%4,%5,%6,%7}, {%8,%9}, {%0,%1,%2,%3};"
                 : "+f"(d[0]), "+f"(d[1]), "+f"(d[2]), "+f"(d[3])
                 : "r"(a0), "r"(a1), "r"(a2), "r"(a3), "r"(b0), "r"(b1));
}
__device__ __forceinline__ unsigned packh2(float lo, float hi) {
    __half2 h = __floats2half2_rn(lo, hi);
    return *(unsigned*)&h;
}

// ---------------- fused BN + conv1x1, tensor-core fp16 hi/lo split + reg double-buffer ----------------
// block tile: 256 px x 64 oc; 256 threads = 8 warps; warp = 32 px (2 m16 tiles) x 64 oc
__global__ __launch_bounds__(256)
void conv1x1_tc_kernel(const float* __restrict__ src0, int C0,
                       const float* __restrict__ src1, int C1,
                       const float* __restrict__ w, const float* __restrict__ bias,
                       int Cout, int hw, float* __restrict__ out, int outStride, int relu,
                       float* __restrict__ mirror) {
    extern __shared__ char cvsm[];
    __half* xh = (__half*)cvsm;            // 32 x PADX halves
    __half* xl = xh + 32*PADX;
    __half* wh = xl + 32*PADX;             // 64 x PADK halves
    __half* wl = wh + 64*PADK;
    const int Cin = C0 + C1;
    int tid = threadIdx.x;
    int lane = tid & 31;
    int wid = tid >> 5;
    int g = lane >> 2, t = lane & 3;
    int p0 = blockIdx.x * 256;
    int n = p0 / hw, hw0 = p0 % hw;
    int ot = blockIdx.y;

    float acc[2][8][4];
    #pragma unroll
    for (int mt = 0; mt < 2; mt++)
        #pragma unroll
        for (int j = 0; j < 8; j++)
            #pragma unroll
            for (int e = 0; e < 4; e++) acc[mt][j][e] = 0.f;

    float4 xv[8];
    float4 wv[2];
    float  sS[8], sT[8];

    #pragma unroll
    for (int it = 0; it < 8; it++) {
        int idx = tid + it * 256;
        int c = idx >> 6, p4 = idx & 63;
        const float* src = (c < C0) ? (src0 + (size_t)(n*C0 + c) * hw)
                                    : (src1 + (size_t)(n*C1 + (c - C0)) * hw);
        xv[it] = *(const float4*)(src + hw0 + p4*4);
        sS[it] = g_S[c]; sT[it] = g_T[c];
    }
    #pragma unroll
    for (int it = 0; it < 2; it++) {
        int idx = tid + it * 256;
        int o = idx >> 3, k4 = idx & 7;
        int oc = ot*64 + o;
        if (oc < Cout) wv[it] = *(const float4*)(w + (size_t)oc * Cin + k4*4);
        else { wv[it].x = 0.f; wv[it].y = 0.f; wv[it].z = 0.f; wv[it].w = 0.f; }
    }

    for (int cc = 0; cc < Cin; cc += 32) {
        #pragma unroll
        for (int it = 0; it < 8; it++) {
            int idx = tid + it * 256;
            int c = idx >> 6, p4 = idx & 63;
            float s = sS[it], tt = sT[it];
            float f0 = xv[it].x*s + tt, f1 = xv[it].y*s + tt;
            float f2 = xv[it].z*s + tt, f3 = xv[it].w*s + tt;
            __half h0 = __float2half_rn(f0), h1 = __float2half_rn(f1);
            __half h2 = __float2half_rn(f2), h3 = __float2half_rn(f3);
            __half l0 = __float2half_rn(f0 - __half2float(h0));
            __half l1 = __float2half_rn(f1 - __half2float(h1));
            __half l2 = __float2half_rn(f2 - __half2float(h2));
            __half l3 = __float2half_rn(f3 - __half2float(h3));
            int off = c*PADX + p4*4;
            *(__half2*)&xh[off]     = __halves2half2(h0, h1);
            *(__half2*)&xh[off + 2] = __halves2half2(h2, h3);
            *(__half2*)&xl[off]     = __halves2half2(l0, l1);
            *(__half2*)&xl[off + 2] = __halves2half2(l2, l3);
        }
        #pragma unroll
        for (int it = 0; it < 2; it++) {
            int idx = tid + it * 256;
            int o = idx >> 3, k4 = idx & 7;
            float4 v = wv[it];
            __half h0 = __float2half_rn(v.x), h1 = __float2half_rn(v.y);
            __half h2 = __float2half_rn(v.z), h3 = __float2half_rn(v.w);
            __half l0 = __float2half_rn(v.x - __half2float(h0));
            __half l1 = __float2half_rn(v.y - __half2float(h1));
            __half l2 = __float2half_rn(v.z - __half2float(h2));
            __half l3 = __float2half_rn(v.w - __half2float(h3));
            int off = o*PADK + k4*4;
            *(__half2*)&wh[off]     = __halves2half2(h0, h1);
            *(__half2*)&wh[off + 2] = __halves2half2(h2, h3);
            *(__half2*)&wl[off]     = __halves2half2(l0, l1);
            *(__half2*)&wl[off + 2] = __halves2half2(l2, l3);
        }
        __syncthreads();

        int nc = cc + 32;
        if (nc < Cin) {
            #pragma unroll
            for (int it = 0; it < 8; it++) {
                int idx = tid + it * 256;
                int c = nc + (idx >> 6); int p4 = idx & 63;
                const float* src = (c < C0) ? (src0 + (size_t)(n*C0 + c) * hw)
                                            : (src1 + (size_t)(n*C1 + (c - C0)) * hw);
                xv[it] = *(const float4*)(src + hw0 + p4*4);
                sS[it] = g_S[c]; sT[it] = g_T[c];
            }
            #pragma unroll
            for (int it = 0; it < 2; it++) {
                int idx = tid + it * 256;
                int o = idx >> 3, k4 = idx & 7;
                int oc = ot*64 + o;
                if (oc < Cout) wv[it] = *(const float4*)(w + (size_t)oc * Cin + nc + k4*4);
                else { wv[it].x = 0.f; wv[it].y = 0.f; wv[it].z = 0.f; wv[it].w = 0.f; }
            }
        }

        #pragma unroll
        for (int kk = 0; kk < 32; kk += 16) {
            unsigned ah[2][4], al[2][4];
            #pragma unroll
            for (int mt = 0; mt < 2; mt++) {
                int m0 = wid*32 + mt*16;
                const __half* pa = xh + (kk + (lane & 7) + ((lane >> 4) << 3))*PADX
                                      + m0 + (((lane >> 3) & 1) << 3);
                const __half* pb = xl + (kk + (lane & 7) + ((lane >> 4) << 3))*PADX
                                      + m0 + (((lane >> 3) & 1) << 3);
                ldm4t(ah[mt][0], ah[mt][1], ah[mt][2], ah[mt][3], pa);
                ldm4t(al[mt][0], al[mt][1], al[mt][2], al[mt][3], pb);
            }
            #pragma unroll
            for (int j = 0; j < 8; j++) {
                int bo = (j*8 + g)*PADK + kk + 2*t;
                unsigned bh0 = *(const unsigned*)(wh + bo);
                unsigned bh1 = *(const unsigned*)(wh + bo + 8);
                unsigned bl0 = *(const unsigned*)(wl + bo);
                unsigned bl1 = *(const unsigned*)(wl + bo + 8);
                #pragma unroll
                for (int mt = 0; mt < 2; mt++) {
                    mma16816(acc[mt][j], ah[mt][0], ah[mt][1], ah[mt][2], ah[mt][3], bh0, bh1);
                    mma16816(acc[mt][j], ah[mt][0], ah[mt][1], ah[mt][2], ah[mt][3], bl0, bl1);
                    mma16816(acc[mt][j], al[mt][0], al[mt][1], al[mt][2], al[mt][3], bh0, bh1);
                }
            }
        }
        __syncthreads();
    }

    #pragma unroll
    for (int mt = 0; mt < 2; mt++) {
        int pr = wid*32 + mt*16 + g;
        #pragma unroll
        for (int j = 0; j < 8; j++) {
            int o = ot*64 + j*8 + 2*t;
            if (o < Cout) {
                float bv = bias[o];
                float v0 = acc[mt][j][0] + bv;
                float v2 = acc[mt][j][2] + bv;
                if (relu) { v0 = fmaxf(v0, 0.f); v2 = fmaxf(v2, 0.f); }
                float* op = out + (size_t)(n*outStride + o) * hw + hw0;
                op[pr] = v0; op[pr + 8] = v2;
                if (mirror != 0 && o >= 64) {
                    float* mp = mirror + (size_t)(n*128 + (o - 64)) * hw + hw0;
                    mp[pr] = v0; mp[pr + 8] = v2;
                }
            }
            if (o + 1 < Cout) {
                float bv = bias[o+1];
                float v1 = acc[mt][j][1] + bv;
                float v3 = acc[mt][j][3] + bv;
                if (relu) { v1 = fmaxf(v1, 0.f); v3 = fmaxf(v3, 0.f); }
                float* op = out + (size_t)(n*outStride + o + 1) * hw + hw0;
                op[pr] = v1; op[pr + 8] = v3;
                if (mirror != 0 && o + 1 >= 64) {
                    float* mp = mirror + (size_t)(n*128 + (o + 1 - 64)) * hw + hw0;
                    mp[pr] = v1; mp[pr + 8] = v3;
                }
            }
        }
    }
}

// ---------------- align-corners bilinear resize ----------------
__global__ void resize_kernel(const float* __restrict__ src, float* __restrict__ dst,
                              int C, int Hs, int Ws, int Hd, int Wd) {
    int idx = blockIdx.x * blockDim.x + threadIdx.x;
    int total = NB * C * Hd * Wd;
    if (idx >= total) return;
    int x = idx % Wd; int y = (idx / Wd) % Hd; int nc = idx / (Wd * Hd);
    float sy = y * (float)(Hs - 1) / (float)(Hd - 1);
    float sx = x * (float)(Ws - 1) / (float)(Wd - 1);
    int y0 = (int)floorf(sy); int x0 = (int)floorf(sx);
    float wy = sy - y0, wx = sx - x0;
    int y1 = min(y0 + 1, Hs - 1), x1 = min(x0 + 1, Ws - 1);
    const float* p = src + (size_t)nc * Hs * Ws;
    float v00 = p[y0*Ws + x0], v01 = p[y0*Ws + x1];
    float v10 = p[y1*Ws + x0], v11 = p[y1*Ws + x1];
    float top = v00 + (v10 - v00) * wy;
    float bot = v01 + (v11 - v01) * wy;
    dst[idx] = top + (bot - top) * wx;
}

// ---------------- grid_sample (border) of temporal_kv ----------------
__global__ void warp_kernel(const float* __restrict__ temporal, const float* __restrict__ mv) {
    int p = blockIdx.x * blockDim.x + threadIdx.x;
    if (p >= NB * HW) return;
    int chunk = blockIdx.y;             // 0..15
    int n = p / HW; int hw = p % HW;
    int h = hw >> 8; int w = hw & 255;
    float xsv = -1.f + 2.f * w / (float)(WW - 1);
    float ysv = -1.f + 2.f * h / (float)(HH - 1);
    float gx = mv[(size_t)(n*2 + 0) * HW + hw] * (2.f / WW) + xsv;
    float gy = ysv - mv[(size_t)(n*2 + 1) * HW + hw] * (2.f / HH);
    float ix = fminf(fmaxf((gx + 1.f) * 0.5f * (WW - 1), 0.f), (float)(WW - 1));
    float iy = fminf(fmaxf((gy + 1.f) * 0.5f * (HH - 1), 0.f), (float)(HH - 1));
    int x0 = (int)floorf(ix), y0 = (int)floorf(iy);
    float wx = ix - x0, wy = iy - y0;
    int x1 = min(x0 + 1, WW - 1), y1 = min(y0 + 1, HH - 1);
    float w00 = (1.f-wy)*(1.f-wx), w01 = (1.f-wy)*wx, w10 = wy*(1.f-wx), w11 = wy*wx;
    int i00 = y0*WW + x0, i01 = y0*WW + x1, i10 = y1*WW + x0, i11 = y1*WW + x1;
    const float* base = temporal + (size_t)(n*128 + chunk*8) * HW;
    float* dst = &g_WARP[(size_t)(n*128 + chunk*8) * HW + hw];
    #pragma unroll
    for (int c = 0; c < 8; c++) {
        const float* pp = base + (size_t)c * HW;
        dst[(size_t)c * HW] = pp[i00]*w00 + pp[i01]*w01 + pp[i10]*w10 + pp[i11]*w11;
    }
}

// ---------------- copy ds_latent tail channels into g_DSS ----------------
__global__ void dscopy_kernel(const float* __restrict__ dsl) {
    int idx = blockIdx.x * blockDim.x + threadIdx.x;
    if (idx >= NB * 3 * DHW) return;
    int n = idx / (3 * DHW); int rem = idx % (3 * DHW);
    int c = rem / DHW; int i = rem % DHW;
    g_DSS[(size_t)(n*128 + 125 + c) * DHW + i] = dsl[(size_t)(n*96 + 93 + c) * DHW + i];
}

// ---------------- warp tree-reduce of (sum, sumsq) ----------------
__device__ __forceinline__ void warp_red2(float& s, float& q) {
    #pragma unroll
    for (int off = 16; off > 0; off >>= 1) {
        s += __shfl_xor_sync(0xffffffffu, s, off);
        q += __shfl_xor_sync(0xffffffffu, q, off);
    }
}

// ---------------- attention gather helpers (registers) ----------------
__device__ __forceinline__ void attn_gather_k(int ci, int tid, int n, int by, int bx,
                                              float4* r) {
    if (ci < 4) {
        #pragma unroll
        for (int it = 0; it < 8; it++) {
            int idx = tid + it * 128;
            int c = idx >> 4, q = idx & 15;
            int y = by - 4 + ci*4 + (q >> 2), x = bx - 4 + (q & 3)*4;
            float4 v;
            if (y >= 0 && y < 256 && x >= 0 && x < 256)
                v = *(const float4*)&g_SU[(size_t)(n*189 + 64 + c) * HW + y*256 + x];
            else { v.x = 0.f; v.y = 0.f; v.z = 0.f; v.w = 0.f; }
            r[it] = v;
        }
    } else {
        const float* src = (ci == 4) ? g_WARP : g_DSE;
        #pragma unroll
        for (int it = 0; it < 8; it++) {
            int idx = tid + it * 128;
            int c = idx >> 4, q = idx & 15;
            int y = by + (q >> 1), x = bx + (q & 1)*4;
            r[it] = *(const float4*)&src[(size_t)(n*128 + c) * HW + y*256 + x];
        }
    }
}
__device__ __forceinline__ void attn_gather_v(int ci, int tid, int n, int by, int bx,
                                              const float* __restrict__ radiance, float4* r) {
    if (ci < 4) {
        #pragma unroll
        for (int it = 0; it < 8; it++) {
            int idx = tid + it * 128;
            int c = idx >> 4, q = idx & 15;
            int y = by - 4 + ci*4 + (q >> 2), x = bx - 4 + (q & 3)*4;
            float4 v;
            if (y >= 0 && y < 256 && x >= 0 && x < 256) {
                int off = y*256 + x;
                v = (c < 61)
                    ? *(const float4*)&g_SU[(size_t)(n*189 + 128 + c) * HW + off]
                    : *(const float4*)&radiance[(size_t)(n*3 + c - 61) * HW + off];
            } else { v.x = 0.f; v.y = 0.f; v.z = 0.f; v.w = 0.f; }
            r[it] = v;
        }
    } else {
        const float* src = (ci == 4) ? g_WARP : g_DSE;
        #pragma unroll
        for (int it = 0; it < 8; it++) {
            int idx = tid + it * 128;
            int c = idx >> 4, q = idx & 15;
            int y = by + (q >> 1), x = bx + (q & 1)*4;
            r[it] = *(const float4*)&src[(size_t)(n*128 + 64 + c) * HW + y*256 + x];
        }
    }
}
__device__ __forceinline__ void attn_store_raw(int ci, int tid, float* Raw, const float4* r) {
    #pragma unroll
    for (int it = 0; it < 8; it++) {
        int idx = tid + it * 128;
        int c = idx >> 4, q = idx & 15;
        int r0 = (ci < 4) ? ((q >> 2)*16 + (q & 3)*4) : (4*q);
        Raw[(r0  )*RSTR + c] = r[it].x;
        Raw[(r0+1)*RSTR + c] = r[it].y;
        Raw[(r0+2)*RSTR + c] = r[it].z;
        Raw[(r0+3)*RSTR + c] = r[it].w;
    }
}

// ---------------- windowed attention: tc fp16 QK/PV, warp-coop LN, reg-prefetch pipeline ----------------
__global__ __launch_bounds__(128)
void attn_kernel(const float* __restrict__ radiance,
                 const float* __restrict__ qg, const float* __restrict__ qb,
                 const float* __restrict__ kg, const float* __restrict__ kb,
                 const float* __restrict__ vg, const float* __restrict__ vb) {
    extern __shared__ char smraw[];
    __half* Qh = (__half*)smraw;           // 64 x PAD
    __half* Kh = Qh + 64*PAD;
    __half* Vh = Kh + 64*PAD;
    float* Raw = (float*)(Vh + 64*PAD);    // 64 x RSTR (single buffer)

    int tid = threadIdx.x;
    int lane = tid & 31;
    int w = tid >> 5;
    int n = blockIdx.x >> 10;
    int l = blockIdx.x & 1023;
    int by = (l >> 5) * 8, bx = (l & 31) * 8;
    int cch = 2*lane;

    // ---- gather Q ----
    #pragma unroll
    for (int it = 0; it < 8; it++) {
        int idx = tid + it * 128;
        int c = idx >> 4, q = idx & 15;
        int y = by + (q >> 1), x = bx + (q & 1)*4;
        int r0 = 4*q;
        float4 v = *(const float4*)&g_SU[(size_t)(n*189 + c) * HW + y*256 + x];
        Raw[(r0  )*RSTR + c] = v.x;
        Raw[(r0+1)*RSTR + c] = v.y;
        Raw[(r0+2)*RSTR + c] = v.z;
        Raw[(r0+3)*RSTR + c] = v.w;
    }
    __syncthreads();

    float4 kreg[8], vreg[8];
    attn_gather_k(0, tid, n, by, bx, kreg);    // prefetch chunk-0 K (overlaps Q LN)

    {
        float gq0 = qg[cch], gq1 = qg[cch+1], bq0 = qb[cch], bq1 = qb[cch+1];
        #pragma unroll
        for (int rr = 0; rr < 16; rr++) {
            int r = w*16 + rr;
            float2 v = *(const float2*)&Raw[r*RSTR + cch];
            float s = v.x + v.y, q2 = v.x*v.x + v.y*v.y;
            warp_red2(s, q2);
            float mu = s * (1.f/64.f);
            float var = q2 * (1.f/64.f) - mu*mu;
            float rs = rsqrtf(var + 1e-5f);
            *(__half2*)&Qh[r*PAD + cch] = __floats2half2_rn(
                ((v.x - mu) * rs * gq0 + bq0) * 0.125f,
                ((v.y - mu) * rs * gq1 + bq1) * 0.125f);
        }
    }
    __syncthreads();

    unsigned qa[4][4];
    {
        int q0 = w * 16;
        #pragma unroll
        for (int kk = 0; kk < 4; kk++) {
            const __half* p = Qh + (q0 + (lane & 15))*PAD + kk*16 + ((lane >> 4) << 3);
            ldm4(qa[kk][0], qa[kk][1], qa[kk][2], qa[kk][3], p);
        }
    }

    float o[8][4];
    #pragma unroll
    for (int t = 0; t < 8; t++)
        #pragma unroll
        for (int j = 0; j < 4; j++) o[t][j] = 0.f;
    float m0 = -1e30f, m1 = -1e30f, l0 = 0.f, l1 = 0.f;

    float gk0 = kg[cch], gk1 = kg[cch+1], bk0 = kb[cch], bk1 = kb[cch+1];
    float gv0 = (cch   < 61) ? vg[cch]   : 0.f;
    float gv1 = (cch+1 < 61) ? vg[cch+1] : 0.f;
    float bv0 = (cch   < 61) ? vb[cch]   : 0.f;
    float bv1 = (cch+1 < 61) ? vb[cch+1] : 0.f;

    for (int ci = 0; ci < 6; ci++) {
        // ---- store prefetched K, sync ----
        attn_store_raw(ci, tid, Raw, kreg);
        __syncthreads();

        // ---- issue V loads (overlap K LN) ----
        attn_gather_v(ci, tid, n, by, bx, radiance, vreg);

        // ---- K LN ----
        #pragma unroll
        for (int rr = 0; rr < 16; rr++) {
            int r = w*16 + rr;
            float2 v = *(const float2*)&Raw[r*RSTR + cch];
            float s = v.x + v.y, q2 = v.x*v.x + v.y*v.y;
            warp_red2(s, q2);
            float mu = s * (1.f/64.f);
            float var = q2 * (1.f/64.f) - mu*mu;
            float rs = rsqrtf(var + 1e-5f);
            *(__half2*)&Kh[r*PAD + cch] = __floats2half2_rn(
                (v.x - mu) * rs * gk0 + bk0,
                (v.y - mu) * rs * gk1 + bk1);
        }
        __syncthreads();

        // ---- store V, sync ----
        attn_store_raw(ci, tid, Raw, vreg);
        __syncthreads();

        // ---- issue next chunk's K loads (overlap V LN + MMAs) ----
        if (ci < 5) attn_gather_k(ci + 1, tid, n, by, bx, kreg);

        // ---- V LN ----
        #pragma unroll
        for (int rr = 0; rr < 16; rr++) {
            int r = w*16 + rr;
            float2 v = *(const float2*)&Raw[r*RSTR + cch];
            float e0 = (cch   < 61) ? v.x : 0.f;
            float e1 = (cch+1 < 61) ? v.y : 0.f;
            float s = e0 + e1, q2 = e0*e0 + e1*e1;
            warp_red2(s, q2);
            float mu = s * (1.f/61.f);
            float var = q2 * (1.f/61.f) - mu*mu;
            float rs = rsqrtf(var + 1e-5f);
            float o0 = (cch   < 61) ? (v.x - mu) * rs * gv0 + bv0 : v.x;
            float o1 = (cch+1 < 61) ? (v.y - mu) * rs * gv1 + bv1 : v.y;
            *(__half2*)&Vh[r*PAD + cch] = __floats2half2_rn(o0, o1);
        }
        __syncthreads();

        // ---- QK MMA ----
        float s[8][4];
        #pragma unroll
        for (int t = 0; t < 8; t++)
            #pragma unroll
            for (int j = 0; j < 4; j++) s[t][j] = 0.f;
        #pragma unroll
        for (int kk = 0; kk < 4; kk++) {
            #pragma unroll
            for (int np = 0; np < 4; np++) {
                unsigned b0, b1, b2, b3;
                const __half* p = Kh + (np*16 + (lane & 7) + ((lane >> 4) << 3))*PAD
                                     + kk*16 + (((lane >> 3) & 1) << 3);
                ldm4(b0, b1, b2, b3, p);
                mma16816(s[2*np],   qa[kk][0], qa[kk][1], qa[kk][2], qa[kk][3], b0, b1);
                mma16816(s[2*np+1], qa[kk][0], qa[kk][1], qa[kk][2], qa[kk][3], b2, b3);
            }
        }

        // ---- online softmax ----
        float mx0 = -1e30f, mx1 = -1e30f;
        #pragma unroll
        for (int t = 0; t < 8; t++) {
            mx0 = fmaxf(mx0, fmaxf(s[t][0], s[t][1]));
            mx1 = fmaxf(mx1, fmaxf(s[t][2], s[t][3]));
        }
        mx0 = fmaxf(mx0, __shfl_xor_sync(0xffffffffu, mx0, 1));
        mx0 = fmaxf(mx0, __shfl_xor_sync(0xffffffffu, mx0, 2));
        mx1 = fmaxf(mx1, __shfl_xor_sync(0xffffffffu, mx1, 1));
        mx1 = fmaxf(mx1, __shfl_xor_sync(0xffffffffu, mx1, 2));
        float mn0 = fmaxf(m0, mx0), mn1 = fmaxf(m1, mx1);
        float corr0 = __expf(m0 - mn0), corr1 = __expf(m1 - mn1);
        m0 = mn0; m1 = mn1;
        float sum0 = 0.f, sum1 = 0.f;
        #pragma unroll
        for (int t = 0; t < 8; t++) {
            s[t][0] = __expf(s[t][0] - m0); s[t][1] = __expf(s[t][1] - m0);
            s[t][2] = __expf(s[t][2] - m1); s[t][3] = __expf(s[t][3] - m1);
            sum0 += s[t][0] + s[t][1];
            sum1 += s[t][2] + s[t][3];
        }
        sum0 += __shfl_xor_sync(0xffffffffu, sum0, 1);
        sum0 += __shfl_xor_sync(0xffffffffu, sum0, 2);
        sum1 += __shfl_xor_sync(0xffffffffu, sum1, 1);
        sum1 += __shfl_xor_sync(0xffffffffu, sum1, 2);
        l0 = l0 * corr0 + sum0;
        l1 = l1 * corr1 + sum1;
        #pragma unroll
        for (int t = 0; t < 8; t++) {
            o[t][0] *= corr0; o[t][1] *= corr0;
            o[t][2] *= corr1; o[t][3] *= corr1;
        }

        // ---- PV MMA ----
        #pragma unroll
        for (int jp = 0; jp < 4; jp++) {
            unsigned a0 = packh2(s[2*jp][0],   s[2*jp][1]);
            unsigned a1 = packh2(s[2*jp][2],   s[2*jp][3]);
            unsigned a2 = packh2(s[2*jp+1][0], s[2*jp+1][1]);
            unsigned a3 = packh2(s[2*jp+1][2], s[2*jp+1][3]);
            #pragma unroll
            for (int np = 0; np < 4; np++) {
                unsigned b0, b1, b2, b3;
                const __half* p = Vh + (jp*16 + (lane & 7) + (((lane >> 3) & 1) << 3))*PAD
                                     + np*16 + ((lane >> 4) << 3);
                ldm4t(b0, b1, b2, b3, p);
                mma16816(o[2*np],   a0, a1, a2, a3, b0, b1);
                mma16816(o[2*np+1], a0, a1, a2, a3, b2, b3);
            }
        }
        // no end-of-loop sync needed: next iteration's Raw store doesn't conflict
        // with Kh/Vh reads, and the post-store sync covers Kh/Vh write hazards.
    }

    float inv0 = 1.f / l0, inv1 = 1.f / l1;
    int r0 = w*16 + (lane >> 2);
    int r1 = r0 + 8;
    int y0 = by + (r0 >> 3), x0 = bx + (r0 & 7);
    int y1 = by + (r1 >> 3), x1 = bx + (r1 & 7);
    #pragma unroll
    for (int t = 0; t < 8; t++) {
        int c = t*8 + 2*(lane & 3);
        g_ATT[(size_t)(n*64 + c    ) * HW + y0*256 + x0] = o[t][0] * inv0;
        g_ATT[(size_t)(n*64 + c + 1) * HW + y0*256 + x0] = o[t][1] * inv0;
        g_ATT[(size_t)(n*64 + c    ) * HW + y1*256 + x1] = o[t][2] * inv1;
        g_ATT[(size_t)(n*64 + c + 1) * HW + y1*256 + x1] = o[t][3] * inv1;
    }
}

// ---------------- output tail: only the g_ATT-sourced channels (float4) ----------------
__global__ void tail_kernel(float* __restrict__ out) {
    int idx = blockIdx.x * blockDim.x + threadIdx.x;
    const int HW4 = HW / 4;
    if (idx >= NB * 3 * HW4) return;
    int n = idx / (3 * HW4); int rem = idx % (3 * HW4);
    int c = rem / HW4; int hw4 = rem % HW4;
    float4 v = *(const float4*)&g_ATT[(size_t)(n*64 + 61 + c) * HW + hw4*4];
    *(float4*)&out[(size_t)(n*64 + 61 + c) * HW + hw4*4] = v;
    *(float4*)&out[(size_t)NB*64*HW + (size_t)(n*128 + 125 + c) * HW + hw4*4] = v;
}

// ---------------- host launcher ----------------
extern "C" void kernel_launch(void* const* d_in, const int* in_sizes, int n_in,
                              void* d_out, int out_size) {
    const float* radiance = (const float*)d_in[0];
    const float* skip     = (const float*)d_in[1];
    const float* dsl      = (const float*)d_in[2];
    const float* temporal = (const float*)d_in[3];
    const float* mv       = (const float*)d_in[4];
    const float* su_bn_g  = (const float*)d_in[5];
    const float* su_bn_b  = (const float*)d_in[6];
    const float* su_w     = (const float*)d_in[7];
    const float* su_b     = (const float*)d_in[8];
    const float* ds_bn_g  = (const float*)d_in[9];
    const float* ds_bn_b  = (const float*)d_in[10];
    const float* ds_w     = (const float*)d_in[11];
    const float* ds_b     = (const float*)d_in[12];
    const float* qln_g    = (const float*)d_in[13];
    const float* qln_b    = (const float*)d_in[14];
    const float* kln_g    = (const float*)d_in[15];
    const float* kln_b    = (const float*)d_in[16];
    const float* vln_g    = (const float*)d_in[17];
    const float* vln_b    = (const float*)d_in[18];
    const float* f1_g     = (const float*)d_in[19];
    const float* f1_b     = (const float*)d_in[20];
    const float* w1       = (const float*)d_in[21];
    const float* b1       = (const float*)d_in[22];
    const float* f2_g     = (const float*)d_in[23];
    const float* f2_b     = (const float*)d_in[24];
    const float* w2       = (const float*)d_in[25];
    const float* b2       = (const float*)d_in[26];
    float* out = (float*)d_out;

    float *dUS, *dSU, *dDSS, *dDSE, *dATT, *dH1;
    cudaGetSymbolAddress((void**)&dUS,  g_US);
    cudaGetSymbolAddress((void**)&dSU,  g_SU);
    cudaGetSymbolAddress((void**)&dDSS, g_DSS);
    cudaGetSymbolAddress((void**)&dDSE, g_DSE);
    cudaGetSymbolAddress((void**)&dATT, g_ATT);
    cudaGetSymbolAddress((void**)&dH1,  g_H1);

    float* outTemporal = out + (size_t)NB*64*HW;

    const int ATTN_SMEM = 3*64*PAD*2 + 64*RSTR*4;   // 44544 B
    cudaFuncSetAttribute(attn_kernel, cudaFuncAttributeMaxDynamicSharedMemorySize, ATTN_SMEM);
    const int CONV_SMEM = (2*32*PADX + 2*64*PADK) * 2;  // 44032 B

    // 1. us = resize(ds_latent, 128->256)
    resize_kernel<<<(NB*96*HW + 255)/256, 256>>>(dsl, dUS, 96, 128, 128, 256, 256);
    // 2-3. su BN stats + conv1x1 -> su_emb (189 ch); ch 64..188 mirrored to temporal_out
    bn_stats1_kernel<<<dim3(192, NSLAB), 256>>>(skip, 96, dUS, 96, HW);
    bn_stats2_kernel<<<192, 32>>>(su_bn_g, su_bn_b, HW);
    conv1x1_tc_kernel<<<dim3((NB*HW)/256, 3), 256, CONV_SMEM>>>(skip, 96, dUS, 96, su_w, su_b, 189, HW, dSU, 189, 0, outTemporal);
    // 4. warped temporal kv
    warp_kernel<<<dim3((NB*HW + 255)/256, 16), 256>>>(temporal, mv);
    // 5-8. ds embedding
    bn_stats1_kernel<<<dim3(96, NSLAB), 256>>>(dsl, 96, (const float*)0, 0, DHW);
    bn_stats2_kernel<<<96, 32>>>(ds_bn_g, ds_bn_b, DHW);
    conv1x1_tc_kernel<<<dim3((NB*DHW)/256, 2), 256, CONV_SMEM>>>(dsl, 96, (const float*)0, 0, ds_w, ds_b, 125, DHW, dDSS, 128, 0, (float*)0);
    dscopy_kernel<<<(NB*3*DHW + 255)/256, 256>>>(dsl);
    resize_kernel<<<(NB*128*HW + 255)/256, 256>>>(dDSS, dDSE, 128, 128, 128, 256, 256);
    // 9. attention (tensor-core)
    attn_kernel<<<NB*1024, 128, ATTN_SMEM>>>(radiance, qln_g, qln_b, kln_g, kln_b, vln_g, vln_b);
    // 10-13. FFN
    bn_stats1_kernel<<<dim3(64, NSLAB), 256>>>(dATT, 64, (const float*)0, 0, HW);
    bn_stats2_kernel<<<64, 32>>>(f1_g, f1_b, HW);
    conv1x1_tc_kernel<<<dim3((NB*HW)/256, 2), 256, CONV_SMEM>>>(dATT, 64, (const float*)0, 0, w1, b1, 128, HW, dH1, 128, 1, (float*)0);
    bn_stats1_kernel<<<dim3(128, NSLAB), 256>>>(dH1, 128, (const float*)0, 0, HW);
    bn_stats2_kernel<<<128, 32>>>(f2_g, f2_b, HW);
    conv1x1_tc_kernel<<<dim3((NB*HW)/256, 1), 256, CONV_SMEM>>>(dH1, 128, (const float*)0, 0, w2, b2, 61, HW, out, 64, 0, (float*)0);
    // 14. remaining tail channels (attention-sourced)
    tail_kernel<<<(NB*3*HW/4 + 255)/256, 256>>>(out);
}

// round 16
// speedup vs baseline: 1.0981x; 1.0451x over previous
#include <cuda_runtime.h>
#include <cuda_fp16.h>
#include <math.h>

#define NB 2
#define HH 256
#define WW 256
#define HW 65536
#define DHW 16384   // 128*128
#define PAD 72      // fp16 row stride for ldmatrix tiles (attention)
#define RSTR 66     // attention raw fp32 row stride
#define NSLAB 16
#define PADX 264    // conv x smem row stride in halves ([k][px], 256 px + 8 pad)
#define PADK 40     // conv w smem row stride in halves ([oc][k])

// ---------------- scratch (static device allocations) ----------------
__device__ float g_US [NB*96 *HW];
__device__ float g_SU [NB*189*HW];
__device__ float g_WARP[NB*128*HW];
__device__ float g_DSS[NB*128*DHW];
__device__ float g_DSE[NB*128*HW];
__device__ float g_ATT[NB*64 *HW];
__device__ float g_H1 [NB*128*HW];
__device__ float g_S[512];           // per-stage regions: su 0, ds 192, f1 288, f2 352
__device__ float g_T[512];
__device__ float g_PSUM[512*NSLAB];
__device__ float g_PSQ [512*NSLAB];

// ---------------- BN stats stage 1 ----------------
__global__ void bn_stats1_kernel(const float* __restrict__ src0, int C0,
                                 const float* __restrict__ src1, int C1,
                                 int hw, int sbase) {
    int c = blockIdx.x;
    int slab = blockIdx.y;
    const float* base; int cs;
    if (c < C0) { base = src0 + (size_t)c * hw; cs = C0; }
    else        { base = src1 + (size_t)(c - C0) * hw; cs = C1; }
    int sl = hw / NSLAB;
    float sum = 0.f, sq = 0.f;
    for (int n = 0; n < NB; n++) {
        const float4* p = (const float4*)(base + (size_t)n * cs * hw + (size_t)slab * sl);
        int nv = sl >> 2;
        for (int i = threadIdx.x; i < nv; i += blockDim.x) {
            float4 v = p[i];
            sum += v.x + v.y + v.z + v.w;
            sq  += v.x*v.x + v.y*v.y + v.z*v.z + v.w*v.w;
        }
    }
    __shared__ float ssum[256], ssq[256];
    ssum[threadIdx.x] = sum; ssq[threadIdx.x] = sq; __syncthreads();
    for (int o = 128; o > 0; o >>= 1) {
        if (threadIdx.x < o) { ssum[threadIdx.x] += ssum[threadIdx.x+o]; ssq[threadIdx.x] += ssq[threadIdx.x+o]; }
        __syncthreads();
    }
    if (threadIdx.x == 0) {
        g_PSUM[(sbase + c)*NSLAB + slab] = ssum[0];
        g_PSQ [(sbase + c)*NSLAB + slab] = ssq[0];
    }
}

// ---------------- BN stats stage 2 ----------------
__global__ void bn_stats2_kernel(const float* __restrict__ g, const float* __restrict__ b,
                                 int hw, int sbase) {
    int c = blockIdx.x;
    if (threadIdx.x == 0) {
        float sum = 0.f, sq = 0.f;
        #pragma unroll
        for (int s = 0; s < NSLAB; s++) {
            sum += g_PSUM[(sbase + c)*NSLAB + s];
            sq  += g_PSQ [(sbase + c)*NSLAB + s];
        }
        float inv = 1.f / (float)(NB * hw);
        float m = sum * inv;
        float v = sq * inv - m * m;
        float s = g[c] * rsqrtf(v + 1e-5f);
        g_S[sbase + c] = s; g_T[sbase + c] = b[c] - m * s;
    }
}

// ---------------- mma helpers ----------------
__device__ __forceinline__ void ldm4(unsigned& r0, unsigned& r1, unsigned& r2, unsigned& r3,
                                     const __half* p) {
    unsigned a = (unsigned)__cvta_generic_to_shared(p);
    asm volatile("ldmatrix.sync.aligned.m8n8.x4.shared.b16 {%0,%1,%2,%3}, [%4];"
                 : "=r"(r0), "=r"(r1), "=r"(r2), "=r"(r3) : "r"(a));
}
__device__ __forceinline__ void ldm4t(unsigned& r0, unsigned& r1, unsigned& r2, unsigned& r3,
                                      const __half* p) {
    unsigned a = (unsigned)__cvta_generic_to_shared(p);
    asm volatile("ldmatrix.sync.aligned.m8n8.x4.trans.shared.b16 {%0,%1,%2,%3}, [%4];"
                 : "=r"(r0), "=r"(r1), "=r"(r2), "=r"(r3) : "r"(a));
}
__device__ __forceinline__ void mma16816(float* d, unsigned a0, unsigned a1, unsigned a2, unsigned a3,
                                         unsigned b0, unsigned b1) {
    asm volatile("mma.sync.aligned.m16n8k16.row.col.f32.f16.f16.f32 "
                 "{%0,%1,%2,%3}, {%4,%5,%6,%7}, {%8,%9}, {%0,%1,%2,%3};"
                 : "+f"(d[0]), "+f"(d[1]), "+f"(d[2]), "+f"(d[3])
                 : "r"(a0), "r"(a1), "r"(a2), "r"(a3), "r"(b0), "r"(b1));
}
__device__ __forceinline__ unsigned packh2(float lo, float hi) {
    __half2 h = __floats2half2_rn(lo, hi);
    return *(unsigned*)&h;
}

// ---------------- fused BN + conv1x1, tensor-core fp16 hi/lo split + reg double-buffer ----------------
__global__ __launch_bounds__(256)
void conv1x1_tc_kernel(const float* __restrict__ src0, int C0,
                       const float* __restrict__ src1, int C1,
                       const float* __restrict__ w, const float* __restrict__ bias,
                       int Cout, int hw, float* __restrict__ out, int outStride, int relu,
                       float* __restrict__ mirror, int sbase) {
    extern __shared__ char cvsm[];
    __half* xh = (__half*)cvsm;            // 32 x PADX halves
    __half* xl = xh + 32*PADX;
    __half* wh = xl + 32*PADX;             // 64 x PADK halves
    __half* wl = wh + 64*PADK;
    const int Cin = C0 + C1;
    int tid = threadIdx.x;
    int lane = tid & 31;
    int wid = tid >> 5;
    int g = lane >> 2, t = lane & 3;
    int p0 = blockIdx.x * 256;
    int n = p0 / hw, hw0 = p0 % hw;
    int ot = blockIdx.y;

    float acc[2][8][4];
    #pragma unroll
    for (int mt = 0; mt < 2; mt++)
        #pragma unroll
        for (int j = 0; j < 8; j++)
            #pragma unroll
            for (int e = 0; e < 4; e++) acc[mt][j][e] = 0.f;

    float4 xv[8];
    float4 wv[2];
    float  sS[8], sT[8];

    #pragma unroll
    for (int it = 0; it < 8; it++) {
        int idx = tid + it * 256;
        int c = idx >> 6, p4 = idx & 63;
        const float* src = (c < C0) ? (src0 + (size_t)(n*C0 + c) * hw)
                                    : (src1 + (size_t)(n*C1 + (c - C0)) * hw);
        xv[it] = *(const float4*)(src + hw0 + p4*4);
        sS[it] = g_S[sbase + c]; sT[it] = g_T[sbase + c];
    }
    #pragma unroll
    for (int it = 0; it < 2; it++) {
        int idx = tid + it * 256;
        int o = idx >> 3, k4 = idx & 7;
        int oc = ot*64 + o;
        if (oc < Cout) wv[it] = *(const float4*)(w + (size_t)oc * Cin + k4*4);
        else { wv[it].x = 0.f; wv[it].y = 0.f; wv[it].z = 0.f; wv[it].w = 0.f; }
    }

    for (int cc = 0; cc < Cin; cc += 32) {
        #pragma unroll
        for (int it = 0; it < 8; it++) {
            int idx = tid + it * 256;
            int c = idx >> 6, p4 = idx & 63;
            float s = sS[it], tt = sT[it];
            float f0 = xv[it].x*s + tt, f1 = xv[it].y*s + tt;
            float f2 = xv[it].z*s + tt, f3 = xv[it].w*s + tt;
            __half h0 = __float2half_rn(f0), h1 = __float2half_rn(f1);
            __half h2 = __float2half_rn(f2), h3 = __float2half_rn(f3);
            __half l0 = __float2half_rn(f0 - __half2float(h0));
            __half l1 = __float2half_rn(f1 - __half2float(h1));
            __half l2 = __float2half_rn(f2 - __half2float(h2));
            __half l3 = __float2half_rn(f3 - __half2float(h3));
            int off = c*PADX + p4*4;
            *(__half2*)&xh[off]     = __halves2half2(h0, h1);
            *(__half2*)&xh[off + 2] = __halves2half2(h2, h3);
            *(__half2*)&xl[off]     = __halves2half2(l0, l1);
            *(__half2*)&xl[off + 2] = __halves2half2(l2, l3);
        }
        #pragma unroll
        for (int it = 0; it < 2; it++) {
            int idx = tid + it * 256;
            int o = idx >> 3, k4 = idx & 7;
            float4 v = wv[it];
            __half h0 = __float2half_rn(v.x), h1 = __float2half_rn(v.y);
            __half h2 = __float2half_rn(v.z), h3 = __float2half_rn(v.w);
            __half l0 = __float2half_rn(v.x - __half2float(h0));
            __half l1 = __float2half_rn(v.y - __half2float(h1));
            __half l2 = __float2half_rn(v.z - __half2float(h2));
            __half l3 = __float2half_rn(v.w - __half2float(h3));
            int off = o*PADK + k4*4;
            *(__half2*)&wh[off]     = __halves2half2(h0, h1);
            *(__half2*)&wh[off + 2] = __halves2half2(h2, h3);
            *(__half2*)&wl[off]     = __halves2half2(l0, l1);
            *(__half2*)&wl[off + 2] = __halves2half2(l2, l3);
        }
        __syncthreads();

        int nc = cc + 32;
        if (nc < Cin) {
            #pragma unroll
            for (int it = 0; it < 8; it++) {
                int idx = tid + it * 256;
                int c = nc + (idx >> 6); int p4 = idx & 63;
                const float* src = (c < C0) ? (src0 + (size_t)(n*C0 + c) * hw)
                                            : (src1 + (size_t)(n*C1 + (c - C0)) * hw);
                xv[it] = *(const float4*)(src + hw0 + p4*4);
                sS[it] = g_S[sbase + c]; sT[it] = g_T[sbase + c];
            }
            #pragma unroll
            for (int it = 0; it < 2; it++) {
                int idx = tid + it * 256;
                int o = idx >> 3, k4 = idx & 7;
                int oc = ot*64 + o;
                if (oc < Cout) wv[it] = *(const float4*)(w + (size_t)oc * Cin + nc + k4*4);
                else { wv[it].x = 0.f; wv[it].y = 0.f; wv[it].z = 0.f; wv[it].w = 0.f; }
            }
        }

        #pragma unroll
        for (int kk = 0; kk < 32; kk += 16) {
            unsigned ah[2][4], al[2][4];
            #pragma unroll
            for (int mt = 0; mt < 2; mt++) {
                int m0 = wid*32 + mt*16;
                const __half* pa = xh + (kk + (lane & 7) + ((lane >> 4) << 3))*PADX
                                      + m0 + (((lane >> 3) & 1) << 3);
                const __half* pb = xl + (kk + (lane & 7) + ((lane >> 4) << 3))*PADX
                                      + m0 + (((lane >> 3) & 1) << 3);
                ldm4t(ah[mt][0], ah[mt][1], ah[mt][2], ah[mt][3], pa);
                ldm4t(al[mt][0], al[mt][1], al[mt][2], al[mt][3], pb);
            }
            #pragma unroll
            for (int j = 0; j < 8; j++) {
                int bo = (j*8 + g)*PADK + kk + 2*t;
                unsigned bh0 = *(const unsigned*)(wh + bo);
                unsigned bh1 = *(const unsigned*)(wh + bo + 8);
                unsigned bl0 = *(const unsigned*)(wl + bo);
                unsigned bl1 = *(const unsigned*)(wl + bo + 8);
                #pragma unroll
                for (int mt = 0; mt < 2; mt++) {
                    mma16816(acc[mt][j], ah[mt][0], ah[mt][1], ah[mt][2], ah[mt][3], bh0, bh1);
                    mma16816(acc[mt][j], ah[mt][0], ah[mt][1], ah[mt][2], ah[mt][3], bl0, bl1);
                    mma16816(acc[mt][j], al[mt][0], al[mt][1], al[mt][2], al[mt][3], bh0, bh1);
                }
            }
        }
        __syncthreads();
    }

    #pragma unroll
    for (int mt = 0; mt < 2; mt++) {
        int pr = wid*32 + mt*16 + g;
        #pragma unroll
        for (int j = 0; j < 8; j++) {
            int o = ot*64 + j*8 + 2*t;
            if (o < Cout) {
                float bv = bias[o];
                float v0 = acc[mt][j][0] + bv;
                float v2 = acc[mt][j][2] + bv;
                if (relu) { v0 = fmaxf(v0, 0.f); v2 = fmaxf(v2, 0.f); }
                float* op = out + (size_t)(n*outStride + o) * hw + hw0;
                op[pr] = v0; op[pr + 8] = v2;
                if (mirror != 0 && o >= 64) {
                    float* mp = mirror + (size_t)(n*128 + (o - 64)) * hw + hw0;
                    mp[pr] = v0; mp[pr + 8] = v2;
                }
            }
            if (o + 1 < Cout) {
                float bv = bias[o+1];
                float v1 = acc[mt][j][1] + bv;
                float v3 = acc[mt][j][3] + bv;
                if (relu) { v1 = fmaxf(v1, 0.f); v3 = fmaxf(v3, 0.f); }
                float* op = out + (size_t)(n*outStride + o + 1) * hw + hw0;
                op[pr] = v1; op[pr + 8] = v3;
                if (mirror != 0 && o + 1 >= 64) {
                    float* mp = mirror + (size_t)(n*128 + (o + 1 - 64)) * hw + hw0;
                    mp[pr] = v1; mp[pr + 8] = v3;
                }
            }
        }
    }
}

// ---------------- align-corners bilinear resize ----------------
__global__ void resize_kernel(const float* __restrict__ src, float* __restrict__ dst,
                              int C, int Hs, int Ws, int Hd, int Wd) {
    int idx = blockIdx.x * blockDim.x + threadIdx.x;
    int total = NB * C * Hd * Wd;
    if (idx >= total) return;
    int x = idx % Wd; int y = (idx / Wd) % Hd; int nc = idx / (Wd * Hd);
    float sy = y * (float)(Hs - 1) / (float)(Hd - 1);
    float sx = x * (float)(Ws - 1) / (float)(Wd - 1);
    int y0 = (int)floorf(sy); int x0 = (int)floorf(sx);
    float wy = sy - y0, wx = sx - x0;
    int y1 = min(y0 + 1, Hs - 1), x1 = min(x0 + 1, Ws - 1);
    const float* p = src + (size_t)nc * Hs * Ws;
    float v00 = p[y0*Ws + x0], v01 = p[y0*Ws + x1];
    float v10 = p[y1*Ws + x0], v11 = p[y1*Ws + x1];
    float top = v00 + (v10 - v00) * wy;
    float bot = v01 + (v11 - v01) * wy;
    dst[idx] = top + (bot - top) * wx;
}

// ---------------- grid_sample (border) of temporal_kv ----------------
__global__ void warp_kernel(const float* __restrict__ temporal, const float* __restrict__ mv) {
    int p = blockIdx.x * blockDim.x + threadIdx.x;
    if (p >= NB * HW) return;
    int chunk = blockIdx.y;             // 0..15
    int n = p / HW; int hw = p % HW;
    int h = hw >> 8; int w = hw & 255;
    float xsv = -1.f + 2.f * w / (float)(WW - 1);
    float ysv = -1.f + 2.f * h / (float)(HH - 1);
    float gx = mv[(size_t)(n*2 + 0) * HW + hw] * (2.f / WW) + xsv;
    float gy = ysv - mv[(size_t)(n*2 + 1) * HW + hw] * (2.f / HH);
    float ix = fminf(fmaxf((gx + 1.f) * 0.5f * (WW - 1), 0.f), (float)(WW - 1));
    float iy = fminf(fmaxf((gy + 1.f) * 0.5f * (HH - 1), 0.f), (float)(HH - 1));
    int x0 = (int)floorf(ix), y0 = (int)floorf(iy);
    float wx = ix - x0, wy = iy - y0;
    int x1 = min(x0 + 1, WW - 1), y1 = min(y0 + 1, HH - 1);
    float w00 = (1.f-wy)*(1.f-wx), w01 = (1.f-wy)*wx, w10 = wy*(1.f-wx), w11 = wy*wx;
    int i00 = y0*WW + x0, i01 = y0*WW + x1, i10 = y1*WW + x0, i11 = y1*WW + x1;
    const float* base = temporal + (size_t)(n*128 + chunk*8) * HW;
    float* dst = &g_WARP[(size_t)(n*128 + chunk*8) * HW + hw];
    #pragma unroll
    for (int c = 0; c < 8; c++) {
        const float* pp = base + (size_t)c * HW;
        dst[(size_t)c * HW] = pp[i00]*w00 + pp[i01]*w01 + pp[i10]*w10 + pp[i11]*w11;
    }
}

// ---------------- copy ds_latent tail channels into g_DSS ----------------
__global__ void dscopy_kernel(const float* __restrict__ dsl) {
    int idx = blockIdx.x * blockDim.x + threadIdx.x;
    if (idx >= NB * 3 * DHW) return;
    int n = idx / (3 * DHW); int rem = idx % (3 * DHW);
    int c = rem / DHW; int i = rem % DHW;
    g_DSS[(size_t)(n*128 + 125 + c) * DHW + i] = dsl[(size_t)(n*96 + 93 + c) * DHW + i];
}

// ---------------- warp tree-reduce of (sum, sumsq) ----------------
__device__ __forceinline__ void warp_red2(float& s, float& q) {
    #pragma unroll
    for (int off = 16; off > 0; off >>= 1) {
        s += __shfl_xor_sync(0xffffffffu, s, off);
        q += __shfl_xor_sync(0xffffffffu, q, off);
    }
}

// ---------------- attention gather helpers (registers) ----------------
__device__ __forceinline__ void attn_gather_k(int ci, int tid, int n, int by, int bx,
                                              float4* r) {
    if (ci < 4) {
        #pragma unroll
        for (int it = 0; it < 8; it++) {
            int idx = tid + it * 128;
            int c = idx >> 4, q = idx & 15;
            int y = by - 4 + ci*4 + (q >> 2), x = bx - 4 + (q & 3)*4;
            float4 v;
            if (y >= 0 && y < 256 && x >= 0 && x < 256)
                v = *(const float4*)&g_SU[(size_t)(n*189 + 64 + c) * HW + y*256 + x];
            else { v.x = 0.f; v.y = 0.f; v.z = 0.f; v.w = 0.f; }
            r[it] = v;
        }
    } else {
        const float* src = (ci == 4) ? g_WARP : g_DSE;
        #pragma unroll
        for (int it = 0; it < 8; it++) {
            int idx = tid + it * 128;
            int c = idx >> 4, q = idx & 15;
            int y = by + (q >> 1), x = bx + (q & 1)*4;
            r[it] = *(const float4*)&src[(size_t)(n*128 + c) * HW + y*256 + x];
        }
    }
}
__device__ __forceinline__ void attn_gather_v(int ci, int tid, int n, int by, int bx,
                                              const float* __restrict__ radiance, float4* r) {
    if (ci < 4) {
        #pragma unroll
        for (int it = 0; it < 8; it++) {
            int idx = tid + it * 128;
            int c = idx >> 4, q = idx & 15;
            int y = by - 4 + ci*4 + (q >> 2), x = bx - 4 + (q & 3)*4;
            float4 v;
            if (y >= 0 && y < 256 && x >= 0 && x < 256) {
                int off = y*256 + x;
                v = (c < 61)
                    ? *(const float4*)&g_SU[(size_t)(n*189 + 128 + c) * HW + off]
                    : *(const float4*)&radiance[(size_t)(n*3 + c - 61) * HW + off];
            } else { v.x = 0.f; v.y = 0.f; v.z = 0.f; v.w = 0.f; }
            r[it] = v;
        }
    } else {
        const float* src = (ci == 4) ? g_WARP : g_DSE;
        #pragma unroll
        for (int it = 0; it < 8; it++) {
            int idx = tid + it * 128;
            int c = idx >> 4, q = idx & 15;
            int y = by + (q >> 1), x = bx + (q & 1)*4;
            r[it] = *(const float4*)&src[(size_t)(n*128 + 64 + c) * HW + y*256 + x];
        }
    }
}
__device__ __forceinline__ void attn_store_raw(int ci, int tid, float* Raw, const float4* r) {
    #pragma unroll
    for (int it = 0; it < 8; it++) {
        int idx = tid + it * 128;
        int c = idx >> 4, q = idx & 15;
        int r0 = (ci < 4) ? ((q >> 2)*16 + (q & 3)*4) : (4*q);
        Raw[(r0  )*RSTR + c] = r[it].x;
        Raw[(r0+1)*RSTR + c] = r[it].y;
        Raw[(r0+2)*RSTR + c] = r[it].z;
        Raw[(r0+3)*RSTR + c] = r[it].w;
    }
}

// ---------------- windowed attention: tc fp16 QK/PV, warp-coop LN, reg-prefetch pipeline ----------------
__global__ __launch_bounds__(128)
void attn_kernel(const float* __restrict__ radiance,
                 const float* __restrict__ qg, const float* __restrict__ qb,
                 const float* __restrict__ kg, const float* __restrict__ kb,
                 const float* __restrict__ vg, const float* __restrict__ vb) {
    extern __shared__ char smraw[];
    __half* Qh = (__half*)smraw;           // 64 x PAD
    __half* Kh = Qh + 64*PAD;
    __half* Vh = Kh + 64*PAD;
    float* Raw = (float*)(Vh + 64*PAD);    // 64 x RSTR (single buffer)

    int tid = threadIdx.x;
    int lane = tid & 31;
    int w = tid >> 5;
    int n = blockIdx.x >> 10;
    int l = blockIdx.x & 1023;
    int by = (l >> 5) * 8, bx = (l & 31) * 8;
    int cch = 2*lane;

    #pragma unroll
    for (int it = 0; it < 8; it++) {
        int idx = tid + it * 128;
        int c = idx >> 4, q = idx & 15;
        int y = by + (q >> 1), x = bx + (q & 1)*4;
        int r0 = 4*q;
        float4 v = *(const float4*)&g_SU[(size_t)(n*189 + c) * HW + y*256 + x];
        Raw[(r0  )*RSTR + c] = v.x;
        Raw[(r0+1)*RSTR + c] = v.y;
        Raw[(r0+2)*RSTR + c] = v.z;
        Raw[(r0+3)*RSTR + c] = v.w;
    }
    __syncthreads();

    float4 kreg[8], vreg[8];
    attn_gather_k(0, tid, n, by, bx, kreg);

    {
        float gq0 = qg[cch], gq1 = qg[cch+1], bq0 = qb[cch], bq1 = qb[cch+1];
        #pragma unroll
        for (int rr = 0; rr < 16; rr++) {
            int r = w*16 + rr;
            float2 v = *(const float2*)&Raw[r*RSTR + cch];
            float s = v.x + v.y, q2 = v.x*v.x + v.y*v.y;
            warp_red2(s, q2);
            float mu = s * (1.f/64.f);
            float var = q2 * (1.f/64.f) - mu*mu;
            float rs = rsqrtf(var + 1e-5f);
            *(__half2*)&Qh[r*PAD + cch] = __floats2half2_rn(
                ((v.x - mu) * rs * gq0 + bq0) * 0.125f,
                ((v.y - mu) * rs * gq1 + bq1) * 0.125f);
        }
    }
    __syncthreads();

    unsigned qa[4][4];
    {
        int q0 = w * 16;
        #pragma unroll
        for (int kk = 0; kk < 4; kk++) {
            const __half* p = Qh + (q0 + (lane & 15))*PAD + kk*16 + ((lane >> 4) << 3);
            ldm4(qa[kk][0], qa[kk][1], qa[kk][2], qa[kk][3], p);
        }
    }

    float o[8][4];
    #pragma unroll
    for (int t = 0; t < 8; t++)
        #pragma unroll
        for (int j = 0; j < 4; j++) o[t][j] = 0.f;
    float m0 = -1e30f, m1 = -1e30f, l0 = 0.f, l1 = 0.f;

    float gk0 = kg[cch], gk1 = kg[cch+1], bk0 = kb[cch], bk1 = kb[cch+1];
    float gv0 = (cch   < 61) ? vg[cch]   : 0.f;
    float gv1 = (cch+1 < 61) ? vg[cch+1] : 0.f;
    float bv0 = (cch   < 61) ? vb[cch]   : 0.f;
    float bv1 = (cch+1 < 61) ? vb[cch+1] : 0.f;

    for (int ci = 0; ci < 6; ci++) {
        attn_store_raw(ci, tid, Raw, kreg);
        __syncthreads();

        attn_gather_v(ci, tid, n, by, bx, radiance, vreg);

        #pragma unroll
        for (int rr = 0; rr < 16; rr++) {
            int r = w*16 + rr;
            float2 v = *(const float2*)&Raw[r*RSTR + cch];
            float s = v.x + v.y, q2 = v.x*v.x + v.y*v.y;
            warp_red2(s, q2);
            float mu = s * (1.f/64.f);
            float var = q2 * (1.f/64.f) - mu*mu;
            float rs = rsqrtf(var + 1e-5f);
            *(__half2*)&Kh[r*PAD + cch] = __floats2half2_rn(
                (v.x - mu) * rs * gk0 + bk0,
                (v.y - mu) * rs * gk1 + bk1);
        }
        __syncthreads();

        attn_store_raw(ci, tid, Raw, vreg);
        __syncthreads();

        if (ci < 5) attn_gather_k(ci + 1, tid, n, by, bx, kreg);

        #pragma unroll
        for (int rr = 0; rr < 16; rr++) {
            int r = w*16 + rr;
            float2 v = *(const float2*)&Raw[r*RSTR + cch];
            float e0 = (cch   < 61) ? v.x : 0.f;
            float e1 = (cch+1 < 61) ? v.y : 0.f;
            float s = e0 + e1, q2 = e0*e0 + e1*e1;
            warp_red2(s, q2);
            float mu = s * (1.f/61.f);
            float var = q2 * (1.f/61.f) - mu*mu;
            float rs = rsqrtf(var + 1e-5f);
            float o0 = (cch   < 61) ? (v.x - mu) * rs * gv0 + bv0 : v.x;
            float o1 = (cch+1 < 61) ? (v.y - mu) * rs * gv1 + bv1 : v.y;
            *(__half2*)&Vh[r*PAD + cch] = __floats2half2_rn(o0, o1);
        }
        __syncthreads();

        float s[8][4];
        #pragma unroll
        for (int t = 0; t < 8; t++)
            #pragma unroll
            for (int j = 0; j < 4; j++) s[t][j] = 0.f;
        #pragma unroll
        for (int kk = 0; kk < 4; kk++) {
            #pragma unroll
            for (int np = 0; np < 4; np++) {
                unsigned b0, b1, b2, b3;
                const __half* p = Kh + (np*16 + (lane & 7) + ((lane >> 4) << 3))*PAD
                                     + kk*16 + (((lane >> 3) & 1) << 3);
                ldm4(b0, b1, b2, b3, p);
                mma16816(s[2*np],   qa[kk][0], qa[kk][1], qa[kk][2], qa[kk][3], b0, b1);
                mma16816(s[2*np+1], qa[kk][0], qa[kk][1], qa[kk][2], qa[kk][3], b2, b3);
            }
        }

        float mx0 = -1e30f, mx1 = -1e30f;
        #pragma unroll
        for (int t = 0; t < 8; t++) {
            mx0 = fmaxf(mx0, fmaxf(s[t][0], s[t][1]));
            mx1 = fmaxf(mx1, fmaxf(s[t][2], s[t][3]));
        }
        mx0 = fmaxf(mx0, __shfl_xor_sync(0xffffffffu, mx0, 1));
        mx0 = fmaxf(mx0, __shfl_xor_sync(0xffffffffu, mx0, 2));
        mx1 = fmaxf(mx1, __shfl_xor_sync(0xffffffffu, mx1, 1));
        mx1 = fmaxf(mx1, __shfl_xor_sync(0xffffffffu, mx1, 2));
        float mn0 = fmaxf(m0, mx0), mn1 = fmaxf(m1, mx1);
        float corr0 = __expf(m0 - mn0), corr1 = __expf(m1 - mn1);
        m0 = mn0; m1 = mn1;
        float sum0 = 0.f, sum1 = 0.f;
        #pragma unroll
        for (int t = 0; t < 8; t++) {
            s[t][0] = __expf(s[t][0] - m0); s[t][1] = __expf(s[t][1] - m0);
            s[t][2] = __expf(s[t][2] - m1); s[t][3] = __expf(s[t][3] - m1);
            sum0 += s[t][0] + s[t][1];
            sum1 += s[t][2] + s[t][3];
        }
        sum0 += __shfl_xor_sync(0xffffffffu, sum0, 1);
        sum0 += __shfl_xor_sync(0xffffffffu, sum0, 2);
        sum1 += __shfl_xor_sync(0xffffffffu, sum1, 1);
        sum1 += __shfl_xor_sync(0xffffffffu, sum1, 2);
        l0 = l0 * corr0 + sum0;
        l1 = l1 * corr1 + sum1;
        #pragma unroll
        for (int t = 0; t < 8; t++) {
            o[t][0] *= corr0; o[t][1] *= corr0;
            o[t][2] *= corr1; o[t][3] *= corr1;
        }

        #pragma unroll
        for (int jp = 0; jp < 4; jp++) {
            unsigned a0 = packh2(s[2*jp][0],   s[2*jp][1]);
            unsigned a1 = packh2(s[2*jp][2],   s[2*jp][3]);
            unsigned a2 = packh2(s[2*jp+1][0], s[2*jp+1][1]);
            unsigned a3 = packh2(s[2*jp+1][2], s[2*jp+1][3]);
            #pragma unroll
            for (int np = 0; np < 4; np++) {
                unsigned b0, b1, b2, b3;
                const __half* p = Vh + (jp*16 + (lane & 7) + (((lane >> 3) & 1) << 3))*PAD
                                     + np*16 + ((lane >> 4) << 3);
                ldm4t(b0, b1, b2, b3, p);
                mma16816(o[2*np],   a0, a1, a2, a3, b0, b1);
                mma16816(o[2*np+1], a0, a1, a2, a3, b2, b3);
            }
        }
    }

    float inv0 = 1.f / l0, inv1 = 1.f / l1;
    int r0 = w*16 + (lane >> 2);
    int r1 = r0 + 8;
    int y0 = by + (r0 >> 3), x0 = bx + (r0 & 7);
    int y1 = by + (r1 >> 3), x1 = bx + (r1 & 7);
    #pragma unroll
    for (int t = 0; t < 8; t++) {
        int c = t*8 + 2*(lane & 3);
        g_ATT[(size_t)(n*64 + c    ) * HW + y0*256 + x0] = o[t][0] * inv0;
        g_ATT[(size_t)(n*64 + c + 1) * HW + y0*256 + x0] = o[t][1] * inv0;
        g_ATT[(size_t)(n*64 + c    ) * HW + y1*256 + x1] = o[t][2] * inv1;
        g_ATT[(size_t)(n*64 + c + 1) * HW + y1*256 + x1] = o[t][3] * inv1;
    }
}

// ---------------- output tail: only the g_ATT-sourced channels (float4) ----------------
__global__ void tail_kernel(float* __restrict__ out) {
    int idx = blockIdx.x * blockDim.x + threadIdx.x;
    const int HW4 = HW / 4;
    if (idx >= NB * 3 * HW4) return;
    int n = idx / (3 * HW4); int rem = idx % (3 * HW4);
    int c = rem / HW4; int hw4 = rem % HW4;
    float4 v = *(const float4*)&g_ATT[(size_t)(n*64 + 61 + c) * HW + hw4*4];
    *(float4*)&out[(size_t)(n*64 + 61 + c) * HW + hw4*4] = v;
    *(float4*)&out[(size_t)NB*64*HW + (size_t)(n*128 + 125 + c) * HW + hw4*4] = v;
}

// ---------------- host launcher (multi-stream fork/join; per-stage BN regions) ----------------
extern "C" void kernel_launch(void* const* d_in, const int* in_sizes, int n_in,
                              void* d_out, int out_size) {
    const float* radiance = (const float*)d_in[0];
    const float* skip     = (const float*)d_in[1];
    const float* dsl      = (const float*)d_in[2];
    const float* temporal = (const float*)d_in[3];
    const float* mv       = (const float*)d_in[4];
    const float* su_bn_g  = (const float*)d_in[5];
    const float* su_bn_b  = (const float*)d_in[6];
    const float* su_w     = (const float*)d_in[7];
    const float* su_b     = (const float*)d_in[8];
    const float* ds_bn_g  = (const float*)d_in[9];
    const float* ds_bn_b  = (const float*)d_in[10];
    const float* ds_w     = (const float*)d_in[11];
    const float* ds_b     = (const float*)d_in[12];
    const float* qln_g    = (const float*)d_in[13];
    const float* qln_b    = (const float*)d_in[14];
    const float* kln_g    = (const float*)d_in[15];
    const float* kln_b    = (const float*)d_in[16];
    const float* vln_g    = (const float*)d_in[17];
    const float* vln_b    = (const float*)d_in[18];
    const float* f1_g     = (const float*)d_in[19];
    const float* f1_b     = (const float*)d_in[20];
    const float* w1       = (const float*)d_in[21];
    const float* b1       = (const float*)d_in[22];
    const float* f2_g     = (const float*)d_in[23];
    const float* f2_b     = (const float*)d_in[24];
    const float* w2       = (const float*)d_in[25];
    const float* b2       = (const float*)d_in[26];
    float* out = (float*)d_out;

    float *dUS, *dSU, *dDSS, *dDSE, *dATT, *dH1;
    cudaGetSymbolAddress((void**)&dUS,  g_US);
    cudaGetSymbolAddress((void**)&dSU,  g_SU);
    cudaGetSymbolAddress((void**)&dDSS, g_DSS);
    cudaGetSymbolAddress((void**)&dDSE, g_DSE);
    cudaGetSymbolAddress((void**)&dATT, g_ATT);
    cudaGetSymbolAddress((void**)&dH1,  g_H1);

    float* outTemporal = out + (size_t)NB*64*HW;

    const int ATTN_SMEM = 3*64*PAD*2 + 64*RSTR*4;   // 44544 B
    const int CONV_SMEM = (2*32*PADX + 2*64*PADK) * 2;  // 44032 B

    // BN stage bases (disjoint regions -> no cross-stream races)
    const int SB_SU = 0, SB_DS = 192, SB_F1 = 288, SB_F2 = 352;

    static cudaStream_t s1 = 0, s2 = 0;
    static cudaEvent_t ev0 = 0, ev1 = 0, ev2 = 0, ev3 = 0, ev4 = 0;
    static int inited = 0;
    if (!inited) {
        cudaStreamCreateWithFlags(&s1, cudaStreamNonBlocking);
        cudaStreamCreateWithFlags(&s2, cudaStreamNonBlocking);
        cudaEventCreateWithFlags(&ev0, cudaEventDisableTiming);
        cudaEventCreateWithFlags(&ev1, cudaEventDisableTiming);
        cudaEventCreateWithFlags(&ev2, cudaEventDisableTiming);
        cudaEventCreateWithFlags(&ev3, cudaEventDisableTiming);
        cudaEventCreateWithFlags(&ev4, cudaEventDisableTiming);
        cudaFuncSetAttribute(attn_kernel, cudaFuncAttributeMaxDynamicSharedMemorySize, ATTN_SMEM);
        inited = 1;
    }

    // ---- fork ----
    cudaEventRecord(ev0, 0);
    cudaStreamWaitEvent(s1, ev0, 0);
    cudaStreamWaitEvent(s2, ev0, 0);

    // branch A (stream 0): su chain
    resize_kernel<<<(NB*96*HW + 255)/256, 256>>>(dsl, dUS, 96, 128, 128, 256, 256);
    bn_stats1_kernel<<<dim3(192, NSLAB), 256>>>(skip, 96, dUS, 96, HW, SB_SU);
    bn_stats2_kernel<<<192, 32>>>(su_bn_g, su_bn_b, HW, SB_SU);
    conv1x1_tc_kernel<<<dim3((NB*HW)/256, 3), 256, CONV_SMEM>>>(skip, 96, dUS, 96, su_w, su_b, 189, HW, dSU, 189, 0, outTemporal, SB_SU);

    // branch B (stream s1): grid-sample warp
    warp_kernel<<<dim3((NB*HW + 255)/256, 16), 256, 0, s1>>>(temporal, mv);

    // branch C (stream s2): ds chain
    bn_stats1_kernel<<<dim3(96, NSLAB), 256, 0, s2>>>(dsl, 96, (const float*)0, 0, DHW, SB_DS);
    bn_stats2_kernel<<<96, 32, 0, s2>>>(ds_bn_g, ds_bn_b, DHW, SB_DS);
    conv1x1_tc_kernel<<<dim3((NB*DHW)/256, 2), 256, CONV_SMEM, s2>>>(dsl, 96, (const float*)0, 0, ds_w, ds_b, 125, DHW, dDSS, 128, 0, (float*)0, SB_DS);
    dscopy_kernel<<<(NB*3*DHW + 255)/256, 256, 0, s2>>>(dsl);
    resize_kernel<<<(NB*128*HW + 255)/256, 256, 0, s2>>>(dDSS, dDSE, 128, 128, 128, 256, 256);

    // ---- join before attention ----
    cudaEventRecord(ev1, s1);
    cudaStreamWaitEvent(0, ev1, 0);
    cudaEventRecord(ev2, s2);
    cudaStreamWaitEvent(0, ev2, 0);

    // attention (stream 0)
    attn_kernel<<<NB*1024, 128, ATTN_SMEM>>>(radiance, qln_g, qln_b, kln_g, kln_b, vln_g, vln_b);

    // fork after attention: tail on s1 overlaps FFN on 0
    cudaEventRecord(ev3, 0);
    cudaStreamWaitEvent(s1, ev3, 0);
    tail_kernel<<<(NB*3*HW/4 + 255)/256, 256, 0, s1>>>(out);

    // FFN chain (stream 0)
    bn_stats1_kernel<<<dim3(64, NSLAB), 256>>>(dATT, 64, (const float*)0, 0, HW, SB_F1);
    bn_stats2_kernel<<<64, 32>>>(f1_g, f1_b, HW, SB_F1);
    conv1x1_tc_kernel<<<dim3((NB*HW)/256, 2), 256, CONV_SMEM>>>(dATT, 64, (const float*)0, 0, w1, b1, 128, HW, dH1, 128, 1, (float*)0, SB_F1);
    bn_stats1_kernel<<<dim3(128, NSLAB), 256>>>(dH1, 128, (const float*)0, 0, HW, SB_F2);
    bn_stats2_kernel<<<128, 32>>>(f2_g, f2_b, HW, SB_F2);
    conv1x1_tc_kernel<<<dim3((NB*HW)/256, 1), 256, CONV_SMEM>>>(dH1, 128, (const float*)0, 0, w2, b2, 61, HW, out, 64, 0, (float*)0, SB_F2);

    // ---- final join ----
    cudaEventRecord(ev4, s1);
    cudaStreamWaitEvent(0, ev4, 0);
}

// round 17
// speedup vs baseline: 1.0996x; 1.0013x over previous
#include <cuda_runtime.h>
#include <cuda_fp16.h>
#include <math.h>

#define NB 2
#define HH 256
#define WW 256
#define HW 65536
#define DHW 16384   // 128*128
#define PAD 72      // fp16 row stride for ldmatrix tiles (attention)
#define RSTR 66     // attention raw fp32 row stride
#define NSLAB 16
#define PADX 264    // conv x smem row stride in halves ([k][px], 256 px + 8 pad)
#define PADK 40     // conv w smem row stride in halves ([oc][k])

// ---------------- scratch (static device allocations) ----------------
__device__ float g_US [NB*96 *HW];
__device__ float g_SU [NB*189*HW];
__device__ float g_WARP[NB*128*HW];
__device__ float g_DSS[NB*128*DHW];
__device__ float g_DSE[NB*128*HW];
__device__ float g_ATT[NB*64 *HW];
__device__ float g_H1 [NB*128*HW];
__device__ float g_S[512];           // per-stage regions: su 0, ds 192, f1 288, f2 352
__device__ float g_T[512];
__device__ float g_PSUM[512*NSLAB];
__device__ float g_PSQ [512*NSLAB];

// ---------------- BN stats stage 1 ----------------
__global__ void bn_stats1_kernel(const float* __restrict__ src0, int C0,
                                 const float* __restrict__ src1, int C1,
                                 int hw, int sbase) {
    int c = blockIdx.x;
    int slab = blockIdx.y;
    const float* base; int cs;
    if (c < C0) { base = src0 + (size_t)c * hw; cs = C0; }
    else        { base = src1 + (size_t)(c - C0) * hw; cs = C1; }
    int sl = hw / NSLAB;
    float sum = 0.f, sq = 0.f;
    for (int n = 0; n < NB; n++) {
        const float4* p = (const float4*)(base + (size_t)n * cs * hw + (size_t)slab * sl);
        int nv = sl >> 2;
        for (int i = threadIdx.x; i < nv; i += blockDim.x) {
            float4 v = p[i];
            sum += v.x + v.y + v.z + v.w;
            sq  += v.x*v.x + v.y*v.y + v.z*v.z + v.w*v.w;
        }
    }
    __shared__ float ssum[256], ssq[256];
    ssum[threadIdx.x] = sum; ssq[threadIdx.x] = sq; __syncthreads();
    for (int o = 128; o > 0; o >>= 1) {
        if (threadIdx.x < o) { ssum[threadIdx.x] += ssum[threadIdx.x+o]; ssq[threadIdx.x] += ssq[threadIdx.x+o]; }
        __syncthreads();
    }
    if (threadIdx.x == 0) {
        g_PSUM[(sbase + c)*NSLAB + slab] = ssum[0];
        g_PSQ [(sbase + c)*NSLAB + slab] = ssq[0];
    }
}

// ---------------- BN stats stage 2 ----------------
__global__ void bn_stats2_kernel(const float* __restrict__ g, const float* __restrict__ b,
                                 int hw, int sbase) {
    int c = blockIdx.x;
    if (threadIdx.x == 0) {
        float sum = 0.f, sq = 0.f;
        #pragma unroll
        for (int s = 0; s < NSLAB; s++) {
            sum += g_PSUM[(sbase + c)*NSLAB + s];
            sq  += g_PSQ [(sbase + c)*NSLAB + s];
        }
        float inv = 1.f / (float)(NB * hw);
        float m = sum * inv;
        float v = sq * inv - m * m;
        float s = g[c] * rsqrtf(v + 1e-5f);
        g_S[sbase + c] = s; g_T[sbase + c] = b[c] - m * s;
    }
}

// ---------------- mma helpers ----------------
__device__ __forceinline__ void ldm4(unsigned& r0, unsigned& r1, unsigned& r2, unsigned& r3,
                                     const __half* p) {
    unsigned a = (unsigned)__cvta_generic_to_shared(p);
    asm volatile("ldmatrix.sync.aligned.m8n8.x4.shared.b16 {%0,%1,%2,%3}, [%4];"
                 : "=r"(r0), "=r"(r1), "=r"(r2), "=r"(r3) : "r"(a));
}
__device__ __forceinline__ void ldm4t(unsigned& r0, unsigned& r1, unsigned& r2, unsigned& r3,
                                      const __half* p) {
    unsigned a = (unsigned)__cvta_generic_to_shared(p);
    asm volatile("ldmatrix.sync.aligned.m8n8.x4.trans.shared.b16 {%0,%1,%2,%3}, [%4];"
                 : "=r"(r0), "=r"(r1), "=r"(r2), "=r"(r3) : "r"(a));
}
__device__ __forceinline__ void mma16816(float* d, unsigned a0, unsigned a1, unsigned a2, unsigned a3,
                                         unsigned b0, unsigned b1) {
    asm volatile("mma.sync.aligned.m16n8k16.row.col.f32.f16.f16.f32 "
                 "{%0,%1,%2,%3}, {%4,%5,%6,%7}, {%8,%9}, {%0,%1,%2,%3};"
                 : "+f"(d[0]), "+f"(d[1]), "+f"(d[2]), "+f"(d[3])
                 : "r"(a0), "r"(a1), "r"(a2), "r"(a3), "r"(b0), "r"(b1));
}
__device__ __forceinline__ unsigned packh2(float lo, float hi) {
    __half2 h = __floats2half2_rn(lo, hi);
    return *(unsigned*)&h;
}

// ---------------- fused BN + conv1x1, tensor-core fp16 hi/lo split + reg double-buffer ----------------
__global__ __launch_bounds__(256)
void conv1x1_tc_kernel(const float* __restrict__ src0, int C0,
                       const float* __restrict__ src1, int C1,
                       const float* __restrict__ w, const float* __restrict__ bias,
                       int Cout, int hw, float* __restrict__ out, int outStride, int relu,
                       float* __restrict__ mirror, int sbase) {
    extern __shared__ char cvsm[];
    __half* xh = (__half*)cvsm;            // 32 x PADX halves
    __half* xl = xh + 32*PADX;
    __half* wh = xl + 32*PADX;             // 64 x PADK halves
    __half* wl = wh + 64*PADK;
    const int Cin = C0 + C1;
    int tid = threadIdx.x;
    int lane = tid & 31;
    int wid = tid >> 5;
    int g = lane >> 2, t = lane & 3;
    int p0 = blockIdx.x * 256;
    int n = p0 / hw, hw0 = p0 % hw;
    int ot = blockIdx.y;

    float acc[2][8][4];
    #pragma unroll
    for (int mt = 0; mt < 2; mt++)
        #pragma unroll
        for (int j = 0; j < 8; j++)
            #pragma unroll
            for (int e = 0; e < 4; e++) acc[mt][j][e] = 0.f;

    float4 xv[8];
    float4 wv[2];
    float  sS[8], sT[8];

    #pragma unroll
    for (int it = 0; it < 8; it++) {
        int idx = tid + it * 256;
        int c = idx >> 6, p4 = idx & 63;
        const float* src = (c < C0) ? (src0 + (size_t)(n*C0 + c) * hw)
                                    : (src1 + (size_t)(n*C1 + (c - C0)) * hw);
        xv[it] = *(const float4*)(src + hw0 + p4*4);
        sS[it] = g_S[sbase + c]; sT[it] = g_T[sbase + c];
    }
    #pragma unroll
    for (int it = 0; it < 2; it++) {
        int idx = tid + it * 256;
        int o = idx >> 3, k4 = idx & 7;
        int oc = ot*64 + o;
        if (oc < Cout) wv[it] = *(const float4*)(w + (size_t)oc * Cin + k4*4);
        else { wv[it].x = 0.f; wv[it].y = 0.f; wv[it].z = 0.f; wv[it].w = 0.f; }
    }

    for (int cc = 0; cc < Cin; cc += 32) {
        #pragma unroll
        for (int it = 0; it < 8; it++) {
            int idx = tid + it * 256;
            int c = idx >> 6, p4 = idx & 63;
            float s = sS[it], tt = sT[it];
            float f0 = xv[it].x*s + tt, f1 = xv[it].y*s + tt;
            float f2 = xv[it].z*s + tt, f3 = xv[it].w*s + tt;
            __half h0 = __float2half_rn(f0), h1 = __float2half_rn(f1);
            __half h2 = __float2half_rn(f2), h3 = __float2half_rn(f3);
            __half l0 = __float2half_rn(f0 - __half2float(h0));
            __half l1 = __float2half_rn(f1 - __half2float(h1));
            __half l2 = __float2half_rn(f2 - __half2float(h2));
            __half l3 = __float2half_rn(f3 - __half2float(h3));
            int off = c*PADX + p4*4;
            *(__half2*)&xh[off]     = __halves2half2(h0, h1);
            *(__half2*)&xh[off + 2] = __halves2half2(h2, h3);
            *(__half2*)&xl[off]     = __halves2half2(l0, l1);
            *(__half2*)&xl[off + 2] = __halves2half2(l2, l3);
        }
        #pragma unroll
        for (int it = 0; it < 2; it++) {
            int idx = tid + it * 256;
            int o = idx >> 3, k4 = idx & 7;
            float4 v = wv[it];
            __half h0 = __float2half_rn(v.x), h1 = __float2half_rn(v.y);
            __half h2 = __float2half_rn(v.z), h3 = __float2half_rn(v.w);
            __half l0 = __float2half_rn(v.x - __half2float(h0));
            __half l1 = __float2half_rn(v.y - __half2float(h1));
            __half l2 = __float2half_rn(v.z - __half2float(h2));
            __half l3 = __float2half_rn(v.w - __half2float(h3));
            int off = o*PADK + k4*4;
            *(__half2*)&wh[off]     = __halves2half2(h0, h1);
            *(__half2*)&wh[off + 2] = __halves2half2(h2, h3);
            *(__half2*)&wl[off]     = __halves2half2(l0, l1);
            *(__half2*)&wl[off + 2] = __halves2half2(l2, l3);
        }
        __syncthreads();

        int nc = cc + 32;
        if (nc < Cin) {
            #pragma unroll
            for (int it = 0; it < 8; it++) {
                int idx = tid + it * 256;
                int c = nc + (idx >> 6); int p4 = idx & 63;
                const float* src = (c < C0) ? (src0 + (size_t)(n*C0 + c) * hw)
                                            : (src1 + (size_t)(n*C1 + (c - C0)) * hw);
                xv[it] = *(const float4*)(src + hw0 + p4*4);
                sS[it] = g_S[sbase + c]; sT[it] = g_T[sbase + c];
            }
            #pragma unroll
            for (int it = 0; it < 2; it++) {
                int idx = tid + it * 256;
                int o = idx >> 3, k4 = idx & 7;
                int oc = ot*64 + o;
                if (oc < Cout) wv[it] = *(const float4*)(w + (size_t)oc * Cin + nc + k4*4);
                else { wv[it].x = 0.f; wv[it].y = 0.f; wv[it].z = 0.f; wv[it].w = 0.f; }
            }
        }

        #pragma unroll
        for (int kk = 0; kk < 32; kk += 16) {
            unsigned ah[2][4], al[2][4];
            #pragma unroll
            for (int mt = 0; mt < 2; mt++) {
                int m0 = wid*32 + mt*16;
                const __half* pa = xh + (kk + (lane & 7) + ((lane >> 4) << 3))*PADX
                                      + m0 + (((lane >> 3) & 1) << 3);
                const __half* pb = xl + (kk + (lane & 7) + ((lane >> 4) << 3))*PADX
                                      + m0 + (((lane >> 3) & 1) << 3);
                ldm4t(ah[mt][0], ah[mt][1], ah[mt][2], ah[mt][3], pa);
                ldm4t(al[mt][0], al[mt][1], al[mt][2], al[mt][3], pb);
            }
            #pragma unroll
            for (int j = 0; j < 8; j++) {
                int bo = (j*8 + g)*PADK + kk + 2*t;
                unsigned bh0 = *(const unsigned*)(wh + bo);
                unsigned bh1 = *(const unsigned*)(wh + bo + 8);
                unsigned bl0 = *(const unsigned*)(wl + bo);
                unsigned bl1 = *(const unsigned*)(wl + bo + 8);
                #pragma unroll
                for (int mt = 0; mt < 2; mt++) {
                    mma16816(acc[mt][j], ah[mt][0], ah[mt][1], ah[mt][2], ah[mt][3], bh0, bh1);
                    mma16816(acc[mt][j], ah[mt][0], ah[mt][1], ah[mt][2], ah[mt][3], bl0, bl1);
                    mma16816(acc[mt][j], al[mt][0], al[mt][1], al[mt][2], al[mt][3], bh0, bh1);
                }
            }
        }
        __syncthreads();
    }

    #pragma unroll
    for (int mt = 0; mt < 2; mt++) {
        int pr = wid*32 + mt*16 + g;
        #pragma unroll
        for (int j = 0; j < 8; j++) {
            int o = ot*64 + j*8 + 2*t;
            if (o < Cout) {
                float bv = bias[o];
                float v0 = acc[mt][j][0] + bv;
                float v2 = acc[mt][j][2] + bv;
                if (relu) { v0 = fmaxf(v0, 0.f); v2 = fmaxf(v2, 0.f); }
                float* op = out + (size_t)(n*outStride + o) * hw + hw0;
                op[pr] = v0; op[pr + 8] = v2;
                if (mirror != 0 && o >= 64) {
                    float* mp = mirror + (size_t)(n*128 + (o - 64)) * hw + hw0;
                    mp[pr] = v0; mp[pr + 8] = v2;
                }
            }
            if (o + 1 < Cout) {
                float bv = bias[o+1];
                float v1 = acc[mt][j][1] + bv;
                float v3 = acc[mt][j][3] + bv;
                if (relu) { v1 = fmaxf(v1, 0.f); v3 = fmaxf(v3, 0.f); }
                float* op = out + (size_t)(n*outStride + o + 1) * hw + hw0;
                op[pr] = v1; op[pr + 8] = v3;
                if (mirror != 0 && o + 1 >= 64) {
                    float* mp = mirror + (size_t)(n*128 + (o + 1 - 64)) * hw + hw0;
                    mp[pr] = v1; mp[pr + 8] = v3;
                }
            }
        }
    }
}

// ---------------- align-corners bilinear resize ----------------
__global__ void resize_kernel(const float* __restrict__ src, float* __restrict__ dst,
                              int C, int Hs, int Ws, int Hd, int Wd) {
    int idx = blockIdx.x * blockDim.x + threadIdx.x;
    int total = NB * C * Hd * Wd;
    if (idx >= total) return;
    int x = idx % Wd; int y = (idx / Wd) % Hd; int nc = idx / (Wd * Hd);
    float sy = y * (float)(Hs - 1) / (float)(Hd - 1);
    float sx = x * (float)(Ws - 1) / (float)(Wd - 1);
    int y0 = (int)floorf(sy); int x0 = (int)floorf(sx);
    float wy = sy - y0, wx = sx - x0;
    int y1 = min(y0 + 1, Hs - 1), x1 = min(x0 + 1, Ws - 1);
    const float* p = src + (size_t)nc * Hs * Ws;
    float v00 = p[y0*Ws + x0], v01 = p[y0*Ws + x1];
    float v10 = p[y1*Ws + x0], v11 = p[y1*Ws + x1];
    float top = v00 + (v10 - v00) * wy;
    float bot = v01 + (v11 - v01) * wy;
    dst[idx] = top + (bot - top) * wx;
}

// ---------------- grid_sample (border) of temporal_kv ----------------
__global__ void warp_kernel(const float* __restrict__ temporal, const float* __restrict__ mv) {
    int p = blockIdx.x * blockDim.x + threadIdx.x;
    if (p >= NB * HW) return;
    int chunk = blockIdx.y;             // 0..15
    int n = p / HW; int hw = p % HW;
    int h = hw >> 8; int w = hw & 255;
    float xsv = -1.f + 2.f * w / (float)(WW - 1);
    float ysv = -1.f + 2.f * h / (float)(HH - 1);
    float gx = mv[(size_t)(n*2 + 0) * HW + hw] * (2.f / WW) + xsv;
    float gy = ysv - mv[(size_t)(n*2 + 1) * HW + hw] * (2.f / HH);
    float ix = fminf(fmaxf((gx + 1.f) * 0.5f * (WW - 1), 0.f), (float)(WW - 1));
    float iy = fminf(fmaxf((gy + 1.f) * 0.5f * (HH - 1), 0.f), (float)(HH - 1));
    int x0 = (int)floorf(ix), y0 = (int)floorf(iy);
    float wx = ix - x0, wy = iy - y0;
    int x1 = min(x0 + 1, WW - 1), y1 = min(y0 + 1, HH - 1);
    float w00 = (1.f-wy)*(1.f-wx), w01 = (1.f-wy)*wx, w10 = wy*(1.f-wx), w11 = wy*wx;
    int i00 = y0*WW + x0, i01 = y0*WW + x1, i10 = y1*WW + x0, i11 = y1*WW + x1;
    const float* base = temporal + (size_t)(n*128 + chunk*8) * HW;
    float* dst = &g_WARP[(size_t)(n*128 + chunk*8) * HW + hw];
    #pragma unroll
    for (int c = 0; c < 8; c++) {
        const float* pp = base + (size_t)c * HW;
        dst[(size_t)c * HW] = pp[i00]*w00 + pp[i01]*w01 + pp[i10]*w10 + pp[i11]*w11;
    }
}

// ---------------- copy ds_latent tail channels into g_DSS ----------------
__global__ void dscopy_kernel(const float* __restrict__ dsl) {
    int idx = blockIdx.x * blockDim.x + threadIdx.x;
    if (idx >= NB * 3 * DHW) return;
    int n = idx / (3 * DHW); int rem = idx % (3 * DHW);
    int c = rem / DHW; int i = rem % DHW;
    g_DSS[(size_t)(n*128 + 125 + c) * DHW + i] = dsl[(size_t)(n*96 + 93 + c) * DHW + i];
}

// ---------------- warp tree-reduce of (sum, sumsq) ----------------
__device__ __forceinline__ void warp_red2(float& s, float& q) {
    #pragma unroll
    for (int off = 16; off > 0; off >>= 1) {
        s += __shfl_xor_sync(0xffffffffu, s, off);
        q += __shfl_xor_sync(0xffffffffu, q, off);
    }
}

// ---------------- attention gather helpers (registers) ----------------
__device__ __forceinline__ void attn_gather_k(int ci, int tid, int n, int by, int bx,
                                              float4* r) {
    if (ci < 4) {
        #pragma unroll
        for (int it = 0; it < 8; it++) {
            int idx = tid + it * 128;
            int c = idx >> 4, q = idx & 15;
            int y = by - 4 + ci*4 + (q >> 2), x = bx - 4 + (q & 3)*4;
            float4 v;
            if (y >= 0 && y < 256 && x >= 0 && x < 256)
                v = *(const float4*)&g_SU[(size_t)(n*189 + 64 + c) * HW + y*256 + x];
            else { v.x = 0.f; v.y = 0.f; v.z = 0.f; v.w = 0.f; }
            r[it] = v;
        }
    } else {
        const float* src = (ci == 4) ? g_WARP : g_DSE;
        #pragma unroll
        for (int it = 0; it < 8; it++) {
            int idx = tid + it * 128;
            int c = idx >> 4, q = idx & 15;
            int y = by + (q >> 1), x = bx + (q & 1)*4;
            r[it] = *(const float4*)&src[(size_t)(n*128 + c) * HW + y*256 + x];
        }
    }
}
__device__ __forceinline__ void attn_gather_v(int ci, int tid, int n, int by, int bx,
                                              const float* __restrict__ radiance, float4* r) {
    if (ci < 4) {
        #pragma unroll
        for (int it = 0; it < 8; it++) {
            int idx = tid + it * 128;
            int c = idx >> 4, q = idx & 15;
            int y = by - 4 + ci*4 + (q >> 2), x = bx - 4 + (q & 3)*4;
            float4 v;
            if (y >= 0 && y < 256 && x >= 0 && x < 256) {
                int off = y*256 + x;
                v = (c < 61)
                    ? *(const float4*)&g_SU[(size_t)(n*189 + 128 + c) * HW + off]
                    : *(const float4*)&radiance[(size_t)(n*3 + c - 61) * HW + off];
            } else { v.x = 0.f; v.y = 0.f; v.z = 0.f; v.w = 0.f; }
            r[it] = v;
        }
    } else {
        const float* src = (ci == 4) ? g_WARP : g_DSE;
        #pragma unroll
        for (int it = 0; it < 8; it++) {
            int idx = tid + it * 128;
            int c = idx >> 4, q = idx & 15;
            int y = by + (q >> 1), x = bx + (q & 1)*4;
            r[it] = *(const float4*)&src[(size_t)(n*128 + 64 + c) * HW + y*256 + x];
        }
    }
}
__device__ __forceinline__ void attn_store_raw(int ci, int tid, float* Raw, const float4* r) {
    #pragma unroll
    for (int it = 0; it < 8; it++) {
        int idx = tid + it * 128;
        int c = idx >> 4, q = idx & 15;
        int r0 = (ci < 4) ? ((q >> 2)*16 + (q & 3)*4) : (4*q);
        Raw[(r0  )*RSTR + c] = r[it].x;
        Raw[(r0+1)*RSTR + c] = r[it].y;
        Raw[(r0+2)*RSTR + c] = r[it].z;
        Raw[(r0+3)*RSTR + c] = r[it].w;
    }
}

// ---------------- windowed attention: tc fp16 QK/PV, warp-coop LN, reg-prefetch pipeline ----------------
__global__ __launch_bounds__(128)
void attn_kernel(const float* __restrict__ radiance,
                 const float* __restrict__ qg, const float* __restrict__ qb,
                 const float* __restrict__ kg, const float* __restrict__ kb,
                 const float* __restrict__ vg, const float* __restrict__ vb) {
    extern __shared__ char smraw[];
    __half* Qh = (__half*)smraw;           // 64 x PAD
    __half* Kh = Qh + 64*PAD;
    __half* Vh = Kh + 64*PAD;
    float* Raw = (float*)(Vh + 64*PAD);    // 64 x RSTR (single buffer)

    int tid = threadIdx.x;
    int lane = tid & 31;
    int w = tid >> 5;
    int n = blockIdx.x >> 10;
    int l = blockIdx.x & 1023;
    int by = (l >> 5) * 8, bx = (l & 31) * 8;
    int cch = 2*lane;

    #pragma unroll
    for (int it = 0; it < 8; it++) {
        int idx = tid + it * 128;
        int c = idx >> 4, q = idx & 15;
        int y = by + (q >> 1), x = bx + (q & 1)*4;
        int r0 = 4*q;
        float4 v = *(const float4*)&g_SU[(size_t)(n*189 + c) * HW + y*256 + x];
        Raw[(r0  )*RSTR + c] = v.x;
        Raw[(r0+1)*RSTR + c] = v.y;
        Raw[(r0+2)*RSTR + c] = v.z;
        Raw[(r0+3)*RSTR + c] = v.w;
    }
    __syncthreads();

    float4 kreg[8], vreg[8];
    attn_gather_k(0, tid, n, by, bx, kreg);

    {
        float gq0 = qg[cch], gq1 = qg[cch+1], bq0 = qb[cch], bq1 = qb[cch+1];
        #pragma unroll
        for (int rr = 0; rr < 16; rr++) {
            int r = w*16 + rr;
            float2 v = *(const float2*)&Raw[r*RSTR + cch];
            float s = v.x + v.y, q2 = v.x*v.x + v.y*v.y;
            warp_red2(s, q2);
            float mu = s * (1.f/64.f);
            float var = q2 * (1.f/64.f) - mu*mu;
            float rs = rsqrtf(var + 1e-5f);
            *(__half2*)&Qh[r*PAD + cch] = __floats2half2_rn(
                ((v.x - mu) * rs * gq0 + bq0) * 0.125f,
                ((v.y - mu) * rs * gq1 + bq1) * 0.125f);
        }
    }
    __syncthreads();

    unsigned qa[4][4];
    {
        int q0 = w * 16;
        #pragma unroll
        for (int kk = 0; kk < 4; kk++) {
            const __half* p = Qh + (q0 + (lane & 15))*PAD + kk*16 + ((lane >> 4) << 3);
            ldm4(qa[kk][0], qa[kk][1], qa[kk][2], qa[kk][3], p);
        }
    }

    float o[8][4];
    #pragma unroll
    for (int t = 0; t < 8; t++)
        #pragma unroll
        for (int j = 0; j < 4; j++) o[t][j] = 0.f;
    float m0 = -1e30f, m1 = -1e30f, l0 = 0.f, l1 = 0.f;

    float gk0 = kg[cch], gk1 = kg[cch+1], bk0 = kb[cch], bk1 = kb[cch+1];
    float gv0 = (cch   < 61) ? vg[cch]   : 0.f;
    float gv1 = (cch+1 < 61) ? vg[cch+1] : 0.f;
    float bv0 = (cch   < 61) ? vb[cch]   : 0.f;
    float bv1 = (cch+1 < 61) ? vb[cch+1] : 0.f;

    for (int ci = 0; ci < 6; ci++) {
        attn_store_raw(ci, tid, Raw, kreg);
        __syncthreads();

        attn_gather_v(ci, tid, n, by, bx, radiance, vreg);

        #pragma unroll
        for (int rr = 0; rr < 16; rr++) {
            int r = w*16 + rr;
            float2 v = *(const float2*)&Raw[r*RSTR + cch];
            float s = v.x + v.y, q2 = v.x*v.x + v.y*v.y;
            warp_red2(s, q2);
            float mu = s * (1.f/64.f);
            float var = q2 * (1.f/64.f) - mu*mu;
            float rs = rsqrtf(var + 1e-5f);
            *(__half2*)&Kh[r*PAD + cch] = __floats2half2_rn(
                (v.x - mu) * rs * gk0 + bk0,
                (v.y - mu) * rs * gk1 + bk1);
        }
        __syncthreads();

        attn_store_raw(ci, tid, Raw, vreg);
        __syncthreads();

        if (ci < 5) attn_gather_k(ci + 1, tid, n, by, bx, kreg);

        #pragma unroll
        for (int rr = 0; rr < 16; rr++) {
            int r = w*16 + rr;
            float2 v = *(const float2*)&Raw[r*RSTR + cch];
            float e0 = (cch   < 61) ? v.x : 0.f;
            float e1 = (cch+1 < 61) ? v.y : 0.f;
            float s = e0 + e1, q2 = e0*e0 + e1*e1;
            warp_red2(s, q2);
            float mu = s * (1.f/61.f);
            float var = q2 * (1.f/61.f) - mu*mu;
            float rs = rsqrtf(var + 1e-5f);
            float o0 = (cch   < 61) ? (v.x - mu) * rs * gv0 + bv0 : v.x;
            float o1 = (cch+1 < 61) ? (v.y - mu) * rs * gv1 + bv1 : v.y;
            *(__half2*)&Vh[r*PAD + cch] = __floats2half2_rn(o0, o1);
        }
        __syncthreads();

        float s[8][4];
        #pragma unroll
        for (int t = 0; t < 8; t++)
            #pragma unroll
            for (int j = 0; j < 4; j++) s[t][j] = 0.f;
        #pragma unroll
        for (int kk = 0; kk < 4; kk++) {
            #pragma unroll
            for (int np = 0; np < 4; np++) {
                unsigned b0, b1, b2, b3;
                const __half* p = Kh + (np*16 + (lane & 7) + ((lane >> 4) << 3))*PAD
                                     + kk*16 + (((lane >> 3) & 1) << 3);
                ldm4(b0, b1, b2, b3, p);
                mma16816(s[2*np],   qa[kk][0], qa[kk][1], qa[kk][2], qa[kk][3], b0, b1);
                mma16816(s[2*np+1], qa[kk][0], qa[kk][1], qa[kk][2], qa[kk][3], b2, b3);
            }
        }

        float mx0 = -1e30f, mx1 = -1e30f;
        #pragma unroll
        for (int t = 0; t < 8; t++) {
            mx0 = fmaxf(mx0, fmaxf(s[t][0], s[t][1]));
            mx1 = fmaxf(mx1, fmaxf(s[t][2], s[t][3]));
        }
        mx0 = fmaxf(mx0, __shfl_xor_sync(0xffffffffu, mx0, 1));
        mx0 = fmaxf(mx0, __shfl_xor_sync(0xffffffffu, mx0, 2));
        mx1 = fmaxf(mx1, __shfl_xor_sync(0xffffffffu, mx1, 1));
        mx1 = fmaxf(mx1, __shfl_xor_sync(0xffffffffu, mx1, 2));
        float mn0 = fmaxf(m0, mx0), mn1 = fmaxf(m1, mx1);
        float corr0 = __expf(m0 - mn0), corr1 = __expf(m1 - mn1);
        m0 = mn0; m1 = mn1;
        float sum0 = 0.f, sum1 = 0.f;
        #pragma unroll
        for (int t = 0; t < 8; t++) {
            s[t][0] = __expf(s[t][0] - m0); s[t][1] = __expf(s[t][1] - m0);
            s[t][2] = __expf(s[t][2] - m1); s[t][3] = __expf(s[t][3] - m1);
            sum0 += s[t][0] + s[t][1];
            sum1 += s[t][2] + s[t][3];
        }
        sum0 += __shfl_xor_sync(0xffffffffu, sum0, 1);
        sum0 += __shfl_xor_sync(0xffffffffu, sum0, 2);
        sum1 += __shfl_xor_sync(0xffffffffu, sum1, 1);
        sum1 += __shfl_xor_sync(0xffffffffu, sum1, 2);
        l0 = l0 * corr0 + sum0;
        l1 = l1 * corr1 + sum1;
        #pragma unroll
        for (int t = 0; t < 8; t++) {
            o[t][0] *= corr0; o[t][1] *= corr0;
            o[t][2] *= corr1; o[t][3] *= corr1;
        }

        #pragma unroll
        for (int jp = 0; jp < 4; jp++) {
            unsigned a0 = packh2(s[2*jp][0],   s[2*jp][1]);
            unsigned a1 = packh2(s[2*jp][2],   s[2*jp][3]);
            unsigned a2 = packh2(s[2*jp+1][0], s[2*jp+1][1]);
            unsigned a3 = packh2(s[2*jp+1][2], s[2*jp+1][3]);
            #pragma unroll
            for (int np = 0; np < 4; np++) {
                unsigned b0, b1, b2, b3;
                const __half* p = Vh + (jp*16 + (lane & 7) + (((lane >> 3) & 1) << 3))*PAD
                                     + np*16 + ((lane >> 4) << 3);
                ldm4t(b0, b1, b2, b3, p);
                mma16816(o[2*np],   a0, a1, a2, a3, b0, b1);
                mma16816(o[2*np+1], a0, a1, a2, a3, b2, b3);
            }
        }
    }

    float inv0 = 1.f / l0, inv1 = 1.f / l1;
    int r0 = w*16 + (lane >> 2);
    int r1 = r0 + 8;
    int y0 = by + (r0 >> 3), x0 = bx + (r0 & 7);
    int y1 = by + (r1 >> 3), x1 = bx + (r1 & 7);
    #pragma unroll
    for (int t = 0; t < 8; t++) {
        int c = t*8 + 2*(lane & 3);
        g_ATT[(size_t)(n*64 + c    ) * HW + y0*256 + x0] = o[t][0] * inv0;
        g_ATT[(size_t)(n*64 + c + 1) * HW + y0*256 + x0] = o[t][1] * inv0;
        g_ATT[(size_t)(n*64 + c    ) * HW + y1*256 + x1] = o[t][2] * inv1;
        g_ATT[(size_t)(n*64 + c + 1) * HW + y1*256 + x1] = o[t][3] * inv1;
    }
}

// ---------------- output tail: only the g_ATT-sourced channels (float4) ----------------
__global__ void tail_kernel(float* __restrict__ out) {
    int idx = blockIdx.x * blockDim.x + threadIdx.x;
    const int HW4 = HW / 4;
    if (idx >= NB * 3 * HW4) return;
    int n = idx / (3 * HW4); int rem = idx % (3 * HW4);
    int c = rem / HW4; int hw4 = rem % HW4;
    float4 v = *(const float4*)&g_ATT[(size_t)(n*64 + 61 + c) * HW + hw4*4];
    *(float4*)&out[(size_t)(n*64 + 61 + c) * HW + hw4*4] = v;
    *(float4*)&out[(size_t)NB*64*HW + (size_t)(n*128 + 125 + c) * HW + hw4*4] = v;
}

// ---------------- host launcher (multi-stream fork/join; per-stage BN regions) ----------------
extern "C" void kernel_launch(void* const* d_in, const int* in_sizes, int n_in,
                              void* d_out, int out_size) {
    const float* radiance = (const float*)d_in[0];
    const float* skip     = (const float*)d_in[1];
    const float* dsl      = (const float*)d_in[2];
    const float* temporal = (const float*)d_in[3];
    const float* mv       = (const float*)d_in[4];
    const float* su_bn_g  = (const float*)d_in[5];
    const float* su_bn_b  = (const float*)d_in[6];
    const float* su_w     = (const float*)d_in[7];
    const float* su_b     = (const float*)d_in[8];
    const float* ds_bn_g  = (const float*)d_in[9];
    const float* ds_bn_b  = (const float*)d_in[10];
    const float* ds_w     = (const float*)d_in[11];
    const float* ds_b     = (const float*)d_in[12];
    const float* qln_g    = (const float*)d_in[13];
    const float* qln_b    = (const float*)d_in[14];
    const float* kln_g    = (const float*)d_in[15];
    const float* kln_b    = (const float*)d_in[16];
    const float* vln_g    = (const float*)d_in[17];
    const float* vln_b    = (const float*)d_in[18];
    const float* f1_g     = (const float*)d_in[19];
    const float* f1_b     = (const float*)d_in[20];
    const float* w1       = (const float*)d_in[21];
    const float* b1       = (const float*)d_in[22];
    const float* f2_g     = (const float*)d_in[23];
    const float* f2_b     = (const float*)d_in[24];
    const float* w2       = (const float*)d_in[25];
    const float* b2       = (const float*)d_in[26];
    float* out = (float*)d_out;

    float *dUS, *dSU, *dDSS, *dDSE, *dATT, *dH1;
    cudaGetSymbolAddress((void**)&dUS,  g_US);
    cudaGetSymbolAddress((void**)&dSU,  g_SU);
    cudaGetSymbolAddress((void**)&dDSS, g_DSS);
    cudaGetSymbolAddress((void**)&dDSE, g_DSE);
    cudaGetSymbolAddress((void**)&dATT, g_ATT);
    cudaGetSymbolAddress((void**)&dH1,  g_H1);

    float* outTemporal = out + (size_t)NB*64*HW;

    const int ATTN_SMEM = 3*64*PAD*2 + 64*RSTR*4;   // 44544 B
    const int CONV_SMEM = (2*32*PADX + 2*64*PADK) * 2;  // 44032 B

    // BN stage bases (disjoint regions -> no cross-stream races)
    const int SB_SU = 0, SB_DS = 192, SB_F1 = 288, SB_F2 = 352;

    static cudaStream_t s1 = 0, s2 = 0;
    static cudaEvent_t ev0 = 0, ev1 = 0, ev2 = 0, ev3 = 0, ev4 = 0;
    static int inited = 0;
    if (!inited) {
        cudaStreamCreateWithFlags(&s1, cudaStreamNonBlocking);
        cudaStreamCreateWithFlags(&s2, cudaStreamNonBlocking);
        cudaEventCreateWithFlags(&ev0, cudaEventDisableTiming);
        cudaEventCreateWithFlags(&ev1, cudaEventDisableTiming);
        cudaEventCreateWithFlags(&ev2, cudaEventDisableTiming);
        cudaEventCreateWithFlags(&ev3, cudaEventDisableTiming);
        cudaEventCreateWithFlags(&ev4, cudaEventDisableTiming);
        cudaFuncSetAttribute(attn_kernel, cudaFuncAttributeMaxDynamicSharedMemorySize, ATTN_SMEM);
        inited = 1;
    }

    // ---- fork ----
    cudaEventRecord(ev0, 0);
    cudaStreamWaitEvent(s1, ev0, 0);
    cudaStreamWaitEvent(s2, ev0, 0);

    // branch A (stream 0): su chain
    resize_kernel<<<(NB*96*HW + 255)/256, 256>>>(dsl, dUS, 96, 128, 128, 256, 256);
    bn_stats1_kernel<<<dim3(192, NSLAB), 256>>>(skip, 96, dUS, 96, HW, SB_SU);
    bn_stats2_kernel<<<192, 32>>>(su_bn_g, su_bn_b, HW, SB_SU);
    conv1x1_tc_kernel<<<dim3((NB*HW)/256, 3), 256, CONV_SMEM>>>(skip, 96, dUS, 96, su_w, su_b, 189, HW, dSU, 189, 0, outTemporal, SB_SU);

    // branch B (stream s1): grid-sample warp
    warp_kernel<<<dim3((NB*HW + 255)/256, 16), 256, 0, s1>>>(temporal, mv);

    // branch C (stream s2): ds chain
    bn_stats1_kernel<<<dim3(96, NSLAB), 256, 0, s2>>>(dsl, 96, (const float*)0, 0, DHW, SB_DS);
    bn_stats2_kernel<<<96, 32, 0, s2>>>(ds_bn_g, ds_bn_b, DHW, SB_DS);
    conv1x1_tc_kernel<<<dim3((NB*DHW)/256, 2), 256, CONV_SMEM, s2>>>(dsl, 96, (const float*)0, 0, ds_w, ds_b, 125, DHW, dDSS, 128, 0, (float*)0, SB_DS);
    dscopy_kernel<<<(NB*3*DHW + 255)/256, 256, 0, s2>>>(dsl);
    resize_kernel<<<(NB*128*HW + 255)/256, 256, 0, s2>>>(dDSS, dDSE, 128, 128, 128, 256, 256);

    // ---- join before attention ----
    cudaEventRecord(ev1, s1);
    cudaStreamWaitEvent(0, ev1, 0);
    cudaEventRecord(ev2, s2);
    cudaStreamWaitEvent(0, ev2, 0);

    // attention (stream 0)
    attn_kernel<<<NB*1024, 128, ATTN_SMEM>>>(radiance, qln_g, qln_b, kln_g, kln_b, vln_g, vln_b);

    // fork after attention: tail on s1 overlaps FFN on 0
    cudaEventRecord(ev3, 0);
    cudaStreamWaitEvent(s1, ev3, 0);
    tail_kernel<<<(NB*3*HW/4 + 255)/256, 256, 0, s1>>>(out);

    // FFN chain (stream 0)
    bn_stats1_kernel<<<dim3(64, NSLAB), 256>>>(dATT, 64, (const float*)0, 0, HW, SB_F1);
    bn_stats2_kernel<<<64, 32>>>(f1_g, f1_b, HW, SB_F1);
    conv1x1_tc_kernel<<<dim3((NB*HW)/256, 2), 256, CONV_SMEM>>>(dATT, 64, (const float*)0, 0, w1, b1, 128, HW, dH1, 128, 1, (float*)0, SB_F1);
    bn_stats1_kernel<<<dim3(128, NSLAB), 256>>>(dH1, 128, (const float*)0, 0, HW, SB_F2);
    bn_stats2_kernel<<<128, 32>>>(f2_g, f2_b, HW, SB_F2);
    conv1x1_tc_kernel<<<dim3((NB*HW)/256, 1), 256, CONV_SMEM>>>(dH1, 128, (const float*)0, 0, w2, b2, 61, HW, out, 64, 0, (float*)0, SB_F2);

    // ---- final join ----
    cudaEventRecord(ev4, s1);
    cudaStreamWaitEvent(0, ev4, 0);
}